// round 13
// baseline (speedup 1.0000x reference)
#include <cuda_runtime.h>
#include <cuda_bf16.h>
#include <math.h>
#include <stdint.h>

#define VNUM   5023
#define NJ     5
#define NB     1024
#define NSHAPE 100
#define NEXPR  50
#define NBETA  150
#define NLMK   68
#define NPOSE  36
#define JR_COLS 453
#define PD_N   (VNUM * 3)      // 15069

#define KP    192              // padded K: 150 betas + 36 pose feats + 6 zero
#define NPAD4 20096            // 157 * 128 >= 4*VNUM

#define VB      10             // vertices per F1 block
#define F1_BLK  504            // 504*10 = 5040 >= 5023
#define NSLOT   8              // Jr accumulator slots (atomic contention split)

// ---- device scratch ----
__device__ float g_Jr8[NSLOT * NJ * JR_COLS];
__device__ float g_relT[NB * NJ * 12];
__device__ __nv_bfloat16 g_A[NB * KP];                // 0.4 MB
__device__ __nv_bfloat16 g_B4[(size_t)NPAD4 * KP];    // 7.7 MB

__device__ __forceinline__ uint32_t smem_u32(const void* p) {
    uint32_t a;
    asm("{ .reg .u64 t; cvta.to.shared.u64 t, %1; cvt.u32.u64 %0, t; }" : "=r"(a) : "l"(p));
    return a;
}

#define LDSM4(R0, R1, R2, R3, ADDR) \
    asm volatile("ldmatrix.sync.aligned.m8n8.x4.shared.b16 {%0,%1,%2,%3}, [%4];" \
        : "=r"(R0), "=r"(R1), "=r"(R2), "=r"(R3) : "r"(ADDR))

#define MMA16816(C, A0, A1, A2, A3, B0, B1) \
    asm volatile("mma.sync.aligned.m16n8k16.row.col.f32.bf16.bf16.f32 " \
        "{%0,%1,%2,%3},{%4,%5,%6,%7},{%8,%9},{%0,%1,%2,%3};" \
        : "+f"((C)[0]), "+f"((C)[1]), "+f"((C)[2]), "+f"((C)[3]) \
        : "r"(A0), "r"(A1), "r"(A2), "r"(A3), "r"(B0), "r"(B1))

#define CP_ASYNC16(DST, SRC) \
    asm volatile("cp.async.cg.shared.global [%0], [%1], 16;" :: "r"(DST), "l"(SRC))
#define CP_ASYNC_WAIT() \
    asm volatile("cp.async.commit_group;\n\tcp.async.wait_group 0;" ::: "memory")

// ============================================================
// Launch 1 — kernZ: zero the 8 Jr accumulator slots
// ============================================================
__global__ void kernZ()
{
    int base = blockIdx.x * NJ * JR_COLS;
    for (int i = threadIdx.x; i < NJ * JR_COLS; i += blockDim.x)
        g_Jr8[base + i] = 0.f;
}

// ============================================================
// Launch 2 — kernF1: fused B4 build + Jr accumulation.
// 504 blocks x 256 threads; each block owns 10 vertices.
// sd rows staged once (used for Jr AND B4); pd slice staged coalesced.
// B4 stores packed as bf16x2 (STG.32). Atomics into slot blockIdx&7.
// ============================================================
__global__ void __launch_bounds__(256) kernF1(
    const float* __restrict__ sd, const float* __restrict__ vt,
    const float* __restrict__ pd, const float* __restrict__ Jreg)
{
    __shared__ float s_sd[VB][456];    // 10 rows x (450 sd | 3 vt | pad)
    __shared__ float s_jr[NJ][VB];
    __shared__ float s_pd[NPOSE][32];  // 36 k-rows x 30 n-values (+pad)
    int tid = threadIdx.x;
    int v0 = blockIdx.x * VB;
    int slot = blockIdx.x & (NSLOT - 1);

    for (int i = tid; i < NJ * VB; i += 256) {
        int j = i / VB, vv = i % VB;
        int v = v0 + vv;
        s_jr[j][vv] = (v < VNUM) ? Jreg[j * VNUM + v] : 0.f;
    }
    // stage 10 sd rows (+vt) coalesced; zero beyond VNUM
    for (int i = tid; i < VB * 456; i += 256) {
        int r = i / 456, c = i - r * 456;
        int v = v0 + r;
        float val = 0.f;
        if (v < VNUM) {
            if (c < 450)      val = sd[v * 450 + c];
            else if (c < 453) val = vt[v * 3 + (c - 450)];
        }
        s_sd[r][c] = val;
    }
    // stage pd slice: row k, lane nn -> pd[k*PD_N + v0*3 + nn]  (coalesced)
    for (int i = tid; i < NPOSE * 32; i += 256) {
        int k = i >> 5, nn = i & 31;
        int ng = v0 * 3 + nn;
        s_pd[k][nn] = (nn < 30 && ng < PD_N) ? pd[(size_t)k * PD_N + ng] : 0.f;
    }
    __syncthreads();

    // --- Jr accumulation ---
    int col0 = tid, col1 = tid + 256;
    float acc[10];
#pragma unroll
    for (int q = 0; q < 10; q++) acc[q] = 0.f;
#pragma unroll
    for (int r = 0; r < VB; r++) {
        float j0 = s_jr[0][r], j1 = s_jr[1][r], j2 = s_jr[2][r];
        float j3 = s_jr[3][r], j4 = s_jr[4][r];
        float x0 = s_sd[r][col0];
        acc[0] = fmaf(j0, x0, acc[0]); acc[1] = fmaf(j1, x0, acc[1]);
        acc[2] = fmaf(j2, x0, acc[2]); acc[3] = fmaf(j3, x0, acc[3]);
        acc[4] = fmaf(j4, x0, acc[4]);
        if (col1 < JR_COLS) {
            float x1 = s_sd[r][col1];
            acc[5] = fmaf(j0, x1, acc[5]); acc[6] = fmaf(j1, x1, acc[6]);
            acc[7] = fmaf(j2, x1, acc[7]); acc[8] = fmaf(j3, x1, acc[8]);
            acc[9] = fmaf(j4, x1, acc[9]);
        }
    }

    // --- B4 build: 40 rows (n = 4v+c) x 96 bf16x2 (packed STG.32) ---
    for (int i = tid; i < 40 * 96; i += 256) {
        int nl = i / 96;
        int kk = (i - nl * 96) * 2;
        int n = v0 * 4 + nl;
        if (n < NPAD4) {
            int vl2 = nl >> 2, c = nl & 3;
            float f0 = 0.f, f1 = 0.f;
            if (c < 3) {
                if (kk < NBETA) {
                    f0 = s_sd[vl2][c * NBETA + kk];
                    f1 = s_sd[vl2][c * NBETA + kk + 1];
                } else if (kk < NBETA + NPOSE) {
                    f0 = s_pd[kk - NBETA][vl2 * 3 + c];
                    f1 = (kk + 1 < NBETA + NPOSE) ? s_pd[kk + 1 - NBETA][vl2 * 3 + c] : 0.f;
                }
            }
            __nv_bfloat162 pk;
            pk.x = __float2bfloat16(f0);
            pk.y = __float2bfloat16(f1);
            *(__nv_bfloat162*)(g_B4 + (size_t)n * KP + kk) = pk;
        }
    }

    // --- atomics into slot (63 CTAs per address) ---
    float* jr = g_Jr8 + slot * NJ * JR_COLS;
#pragma unroll
    for (int j = 0; j < NJ; j++) {
        atomicAdd(&jr[j * JR_COLS + col0], acc[j]);
        if (col1 < JR_COLS) atomicAdd(&jr[j * JR_COLS + col1], acc[5 + j]);
    }
}

// ============================================================
// Launch 3 — kernB: joints, Rodrigues, chain -> g_relT + bf16 A rows.
// 32 blocks x 32 threads (1 batch/thread).  Sums the 8 Jr slots.
// ============================================================
#define BP 153

__global__ void __launch_bounds__(32) kernB(
    const float* __restrict__ shape, const float* __restrict__ expr,
    const float* __restrict__ pose, const float* __restrict__ eye,
    const float* __restrict__ neck)
{
    __shared__ float s_jr[NJ * JR_COLS];
    __shared__ float s_beta[32 * BP];
    int tid = threadIdx.x;
    int b0 = blockIdx.x * 32;

    for (int i = tid; i < NJ * JR_COLS; i += 32) {
        float s = 0.f;
#pragma unroll
        for (int t = 0; t < NSLOT; t++) s += g_Jr8[t * NJ * JR_COLS + i];
        s_jr[i] = s;
    }
    for (int i = tid; i < 32 * NSHAPE; i += 32)
        s_beta[(i / NSHAPE) * BP + (i % NSHAPE)] = shape[b0 * NSHAPE + i];
    for (int i = tid; i < 32 * NEXPR; i += 32)
        s_beta[(i / NEXPR) * BP + NSHAPE + (i % NEXPR)] = expr[b0 * NEXPR + i];
    __syncthreads();

    int b = b0 + tid;
    const float* myb = s_beta + tid * BP;

    float J[NJ][3];
#pragma unroll
    for (int j = 0; j < NJ; j++)
#pragma unroll
        for (int c = 0; c < 3; c++) J[j][c] = s_jr[j * JR_COLS + 450 + c];

    for (int l = 0; l < NBETA; l++) {
        float blv = myb[l];
#pragma unroll
        for (int j = 0; j < NJ; j++)
#pragma unroll
            for (int c = 0; c < 3; c++) J[j][c] = fmaf(s_jr[j * JR_COLS + l], blv, J[j][c]);
    }

    float fp[15];
    fp[0] = pose[b * 6 + 0]; fp[1] = pose[b * 6 + 1]; fp[2] = pose[b * 6 + 2];
    fp[3] = neck[0]; fp[4] = neck[1]; fp[5] = neck[2];
    fp[6] = pose[b * 6 + 3]; fp[7] = pose[b * 6 + 4]; fp[8] = pose[b * 6 + 5];
#pragma unroll
    for (int k = 0; k < 6; k++) fp[9 + k] = eye[k];

    float R[NJ][9];
#pragma unroll
    for (int j = 0; j < NJ; j++) {
        float x = fp[j * 3 + 0], y = fp[j * 3 + 1], z = fp[j * 3 + 2];
        float xa = x + 1e-8f, ya = y + 1e-8f, za = z + 1e-8f;
        float ang = sqrtf(xa * xa + ya * ya + za * za);
        float inv = 1.f / ang;
        float rx = x * inv, ry = y * inv, rz = z * inv;
        float s, c;
        sincosf(ang, &s, &c);
        float t = 1.f - c;
        R[j][0] = 1.f - t * (ry * ry + rz * rz);
        R[j][1] = -s * rz + t * rx * ry;
        R[j][2] =  s * ry + t * rx * rz;
        R[j][3] =  s * rz + t * rx * ry;
        R[j][4] = 1.f - t * (rx * rx + rz * rz);
        R[j][5] = -s * rx + t * ry * rz;
        R[j][6] = -s * ry + t * rx * rz;
        R[j][7] =  s * rx + t * ry * rz;
        R[j][8] = 1.f - t * (rx * rx + ry * ry);
    }

    // --- g_A row: [betas(150) | pose_feature(36) | 0 pad(6)] bf16 ---
    {
        __nv_bfloat16* arow = g_A + (size_t)b * KP;
#pragma unroll 2
        for (int l = 0; l < NBETA; l++) arow[l] = __float2bfloat16(myb[l]);
#pragma unroll
        for (int j = 1; j < NJ; j++)
#pragma unroll
            for (int k = 0; k < 9; k++) {
                float d = (k == 0 || k == 4 || k == 8) ? 1.f : 0.f;
                arow[NBETA + (j - 1) * 9 + k] = __float2bfloat16(R[j][k] - d);
            }
#pragma unroll
        for (int k = NBETA + NPOSE; k < KP; k++) arow[k] = __float2bfloat16(0.f);
    }

    const int par[NJ] = { -1, 0, 1, 1, 1 };
    float rel[NJ][3];
#pragma unroll
    for (int c = 0; c < 3; c++) rel[0][c] = J[0][c];
#pragma unroll
    for (int j = 1; j < NJ; j++)
#pragma unroll
        for (int c = 0; c < 3; c++) rel[j][c] = J[j][c] - J[par[j]][c];

    float cR[NJ][9], ct[NJ][3];
#pragma unroll
    for (int k = 0; k < 9; k++) cR[0][k] = R[0][k];
#pragma unroll
    for (int c = 0; c < 3; c++) ct[0][c] = rel[0][c];
#pragma unroll
    for (int j = 1; j < NJ; j++) {
        int p = par[j];
#pragma unroll
        for (int r = 0; r < 3; r++) {
#pragma unroll
            for (int c = 0; c < 3; c++)
                cR[j][r * 3 + c] = cR[p][r * 3 + 0] * R[j][0 + c]
                                 + cR[p][r * 3 + 1] * R[j][3 + c]
                                 + cR[p][r * 3 + 2] * R[j][6 + c];
            ct[j][r] = cR[p][r * 3 + 0] * rel[j][0] + cR[p][r * 3 + 1] * rel[j][1]
                     + cR[p][r * 3 + 2] * rel[j][2] + ct[p][r];
        }
    }

#pragma unroll
    for (int j = 0; j < NJ; j++)
#pragma unroll
        for (int r = 0; r < 3; r++) {
            float tr = ct[j][r] - (cR[j][r * 3 + 0] * J[j][0] + cR[j][r * 3 + 1] * J[j][1]
                                 + cR[j][r * 3 + 2] * J[j][2]);
            g_relT[b * 60 + j * 12 + r * 4 + 0] = cR[j][r * 3 + 0];
            g_relT[b * 60 + j * 12 + r * 4 + 1] = cR[j][r * 3 + 1];
            g_relT[b * 60 + j * 12 + r * 4 + 2] = cR[j][r * 3 + 2];
            g_relT[b * 60 + j * 12 + r * 4 + 3] = tr;
        }
}

// ============================================================
// Launch 4 — kernG: C[128b x 128n] = A @ B4^T (mma.sync bf16)
// + fused LBS epilogue.  512 threads = 16 warps (4m x 4n), warp
// tile 32b x 32n (proven shape), 2 CTAs/SM -> 32 warps/SM.
// smem mainloop: A@0 (128x400B=51200), B@51200 (51200) -> 102400
// epilogue reuse: sC@0 (128x132 f32=67584), relT@67584 (30720),
//                 w@98304 (640), vt@98944 (384)
// ============================================================
#define SMB_OFF 51200
#define SM_TOT  102400

__global__ void __launch_bounds__(512, 2) kernG(
    const float* __restrict__ vt, const float* __restrict__ lw,
    float* __restrict__ out)
{
    extern __shared__ char smr[];
    uint32_t sb = smem_u32(smr);
    int tid = threadIdx.x;
    int lane = tid & 31, w = tid >> 5;
    int wm = w & 3, wn = w >> 2;          // 4m x 4n grid, warp tile 32b x 32n
    int n0 = blockIdx.x * 128;
    int b0 = blockIdx.y * 128;
    int v0 = n0 >> 2;                     // 32 vertices per tile

    // --- stage A,B tiles (each 128 x 24 uint4, pitch 400B) via cp.async ---
    {
        const uint4* gA4 = (const uint4*)(g_A + (size_t)b0 * KP);
        const uint4* gB4 = (const uint4*)(g_B4 + (size_t)n0 * KP);
        for (int i = tid; i < 128 * 24; i += 512) {
            int row = i / 24, q = i - row * 24;
            CP_ASYNC16(sb + row * 400 + q * 16, gA4 + i);
            CP_ASYNC16(sb + SMB_OFF + row * 400 + q * 16, gB4 + i);
        }
        CP_ASYNC_WAIT();
    }
    __syncthreads();

    float acc[2][4][4];
#pragma unroll
    for (int a = 0; a < 2; a++)
#pragma unroll
        for (int j = 0; j < 4; j++)
#pragma unroll
            for (int k = 0; k < 4; k++) acc[a][j][k] = 0.f;

    int lrow = lane & 15;
    uint32_t koff = (uint32_t)((lane >> 4) * 16);
    uint32_t aBase = sb + (wm * 32 + lrow) * 400 + koff;
    uint32_t bBase = sb + SMB_OFF + (wn * 32 + lrow) * 400 + koff;

#pragma unroll
    for (int ks = 0; ks < 12; ks++) {
        uint32_t kb = (uint32_t)ks * 32u;
        uint32_t ra[2][4], rb[2][4];
        LDSM4(ra[0][0], ra[0][1], ra[0][2], ra[0][3], aBase + kb);
        LDSM4(ra[1][0], ra[1][1], ra[1][2], ra[1][3], aBase + 16 * 400 + kb);
        LDSM4(rb[0][0], rb[0][1], rb[0][2], rb[0][3], bBase + kb);
        LDSM4(rb[1][0], rb[1][1], rb[1][2], rb[1][3], bBase + 16 * 400 + kb);
#pragma unroll
        for (int a = 0; a < 2; a++)
#pragma unroll
            for (int jj = 0; jj < 2; jj++) {
                MMA16816(acc[a][jj * 2],     ra[a][0], ra[a][1], ra[a][2], ra[a][3],
                         rb[jj][0], rb[jj][2]);
                MMA16816(acc[a][jj * 2 + 1], ra[a][0], ra[a][1], ra[a][2], ra[a][3],
                         rb[jj][1], rb[jj][3]);
            }
    }

    __syncthreads();   // done reading A/B smem

    // --- write accumulators to sC [128 x 132] f32 ---
    float* sC = (float*)smr;
#pragma unroll
    for (int a = 0; a < 2; a++) {
        int r = wm * 32 + a * 16 + (lane >> 2);
        int cb = wn * 32 + (lane & 3) * 2;
#pragma unroll
        for (int j = 0; j < 4; j++) {
            int c = cb + j * 8;
            sC[r * 132 + c]           = acc[a][j][0];
            sC[r * 132 + c + 1]       = acc[a][j][1];
            sC[(r + 8) * 132 + c]     = acc[a][j][2];
            sC[(r + 8) * 132 + c + 1] = acc[a][j][3];
        }
    }

    // --- stage relT / weights / template ---
    float* sRT = (float*)(smr + 67584);
    for (int i = tid; i < 128 * 60; i += 512) sRT[i] = g_relT[b0 * 60 + i];
    float* sW = (float*)(smr + 98304);
    if (tid < 32 * NJ) {
        int vl = tid / NJ;
        int v = v0 + vl;
        sW[tid] = (v < VNUM) ? lw[v * NJ + (tid % NJ)] : 0.f;
    }
    float* sVT = (float*)(smr + 98944);
    if (tid < 96) {
        int vl = tid / 3;
        int v = v0 + vl;
        sVT[tid] = (v < VNUM) ? vt[v * 3 + (tid % 3)] : 0.f;
    }
    __syncthreads();

    // --- epilogue: fixed vertex per thread (vl = lane); 8 bl each ---
    {
        int vl = lane;
        int v = v0 + vl;
        bool ok = (v < VNUM);
        float w0 = sW[vl * NJ + 0], w1 = sW[vl * NJ + 1], w2 = sW[vl * NJ + 2];
        float w3 = sW[vl * NJ + 3], w4 = sW[vl * NJ + 4];
        float vtx = sVT[vl * 3 + 0], vty = sVT[vl * 3 + 1], vtz = sVT[vl * 3 + 2];

#pragma unroll 4
        for (int it = 0; it < 8; it++) {
            int bl = it * 16 + w;          // warp-uniform batch row
            float4 cv = *(const float4*)(sC + bl * 132 + vl * 4);
            const float4* rt4 = (const float4*)(sRT + bl * 60);   // broadcast
            float4 T4[3];
#pragma unroll
            for (int q = 0; q < 3; q++) {
                float4 r0 = rt4[q], r1 = rt4[3 + q], r2 = rt4[6 + q];
                float4 r3 = rt4[9 + q], r4 = rt4[12 + q];
                T4[q].x = fmaf(w0, r0.x, fmaf(w1, r1.x, fmaf(w2, r2.x, fmaf(w3, r3.x, w4 * r4.x))));
                T4[q].y = fmaf(w0, r0.y, fmaf(w1, r1.y, fmaf(w2, r2.y, fmaf(w3, r3.y, w4 * r4.y))));
                T4[q].z = fmaf(w0, r0.z, fmaf(w1, r1.z, fmaf(w2, r2.z, fmaf(w3, r3.z, w4 * r4.z))));
                T4[q].w = fmaf(w0, r0.w, fmaf(w1, r1.w, fmaf(w2, r2.w, fmaf(w3, r3.w, w4 * r4.w))));
            }
            float px = cv.x + vtx;
            float py = cv.y + vty;
            float pz = cv.z + vtz;
            float ox = fmaf(T4[0].x, px, fmaf(T4[0].y, py, fmaf(T4[0].z, pz, T4[0].w)));
            float oy = fmaf(T4[1].x, px, fmaf(T4[1].y, py, fmaf(T4[1].z, pz, T4[1].w)));
            float oz = fmaf(T4[2].x, px, fmaf(T4[2].y, py, fmaf(T4[2].z, pz, T4[2].w)));
            if (ok) {
                size_t base = ((size_t)(b0 + bl) * VNUM + v) * 3;
                out[base + 0] = ox; out[base + 1] = oy; out[base + 2] = oz;
            }
        }
    }
}

// ============================================================
// Launch 5 — kernD: landmark gather
// ============================================================
__global__ void kernD(const int* __restrict__ land, const float* __restrict__ verts,
                      float* __restrict__ lmk)
{
    int i = blockIdx.x * blockDim.x + threadIdx.x;
    if (i >= NB * NLMK) return;
    int b = i / NLMK, k = i % NLMK;
    int v = land[k];
    size_t src = ((size_t)b * VNUM + v) * 3;
    size_t dst = (size_t)i * 3;
    lmk[dst + 0] = verts[src + 0];
    lmk[dst + 1] = verts[src + 1];
    lmk[dst + 2] = verts[src + 2];
}

// ============================================================
extern "C" void kernel_launch(void* const* d_in, const int* in_sizes, int n_in,
                              void* d_out, int out_size)
{
    const float* shape = (const float*)d_in[0];
    const float* expr  = (const float*)d_in[1];
    const float* pose  = (const float*)d_in[2];
    const int*   land  = (const int*)  d_in[3];
    const float* vt    = (const float*)d_in[4];
    const float* sd    = (const float*)d_in[5];
    const float* pd    = (const float*)d_in[6];
    const float* Jreg  = (const float*)d_in[7];
    const float* lw    = (const float*)d_in[8];
    const float* eye   = (const float*)d_in[9];
    const float* neck  = (const float*)d_in[10];
    float* out = (float*)d_out;

    cudaFuncSetAttribute(kernG, cudaFuncAttributeMaxDynamicSharedMemorySize, SM_TOT);

    kernZ<<<NSLOT, 256>>>();                              // launch 1
    kernF1<<<F1_BLK, 256>>>(sd, vt, pd, Jreg);            // launch 2
    kernB<<<NB / 32, 32>>>(shape, expr, pose, eye, neck); // launch 3
    dim3 gg(NPAD4 / 128, NB / 128);
    kernG<<<gg, 512, SM_TOT>>>(vt, lw, out);              // launch 4  <- profiled
    float* lmk = out + (size_t)NB * VNUM * 3;
    kernD<<<(NB * NLMK + 255) / 256, 256>>>(land, out, lmk);  // launch 5
}

// round 14
// speedup vs baseline: 1.0347x; 1.0347x over previous
#include <cuda_runtime.h>
#include <cuda_bf16.h>
#include <math.h>
#include <stdint.h>

#define VNUM   5023
#define NJ     5
#define NB     1024
#define NSHAPE 100
#define NEXPR  50
#define NBETA  150
#define NLMK   68
#define NPOSE  36
#define JR_COLS 453
#define PD_N   (VNUM * 3)      // 15069

#define KP    192              // padded K: 150 betas + 36 pose feats + 6 zero
#define NPAD3 15168            // 79 * 192 >= 3*VNUM = 15069

#define VB      10             // vertices per F1 block
#define F1_BLK  504            // 504*10 = 5040 >= 5023
#define NSLOT   8              // Jr accumulator slots (atomic contention split)

// ---- device scratch ----
__device__ float g_Jr8[NSLOT * NJ * JR_COLS];         // zero at load; kernD re-zeros
__device__ float g_relT[NB * NJ * 12];
__device__ __nv_bfloat16 g_A[NB * KP];                // 0.4 MB
__device__ __nv_bfloat16 g_B3[(size_t)NPAD3 * KP];    // 5.8 MB (rows >= 15120 stay 0)

__device__ __forceinline__ uint32_t smem_u32(const void* p) {
    uint32_t a;
    asm("{ .reg .u64 t; cvta.to.shared.u64 t, %1; cvt.u32.u64 %0, t; }" : "=r"(a) : "l"(p));
    return a;
}

#define LDSM4(R0, R1, R2, R3, ADDR) \
    asm volatile("ldmatrix.sync.aligned.m8n8.x4.shared.b16 {%0,%1,%2,%3}, [%4];" \
        : "=r"(R0), "=r"(R1), "=r"(R2), "=r"(R3) : "r"(ADDR))

#define MMA16816(C, A0, A1, A2, A3, B0, B1) \
    asm volatile("mma.sync.aligned.m16n8k16.row.col.f32.bf16.bf16.f32 " \
        "{%0,%1,%2,%3},{%4,%5,%6,%7},{%8,%9},{%0,%1,%2,%3};" \
        : "+f"((C)[0]), "+f"((C)[1]), "+f"((C)[2]), "+f"((C)[3]) \
        : "r"(A0), "r"(A1), "r"(A2), "r"(A3), "r"(B0), "r"(B1))

#define CP_ASYNC16(DST, SRC) \
    asm volatile("cp.async.cg.shared.global [%0], [%1], 16;" :: "r"(DST), "l"(SRC))
#define CP_ASYNC_WAIT() \
    asm volatile("cp.async.commit_group;\n\tcp.async.wait_group 0;" ::: "memory")

// ============================================================
// Launch 1 — kernF1: fused B3 build + Jr accumulation.
// 504 blocks x 256 threads; each block owns 10 vertices.
// sd rows staged once (used for Jr AND B3); pd slice staged coalesced.
// B3 stores packed as bf16x2 (STG.32). Atomics into slot blockIdx&7.
// Slots were zeroed by the previous graph replay's kernD (load-time
// zero on the very first call).
// ============================================================
__global__ void __launch_bounds__(256) kernF1(
    const float* __restrict__ sd, const float* __restrict__ vt,
    const float* __restrict__ pd, const float* __restrict__ Jreg)
{
    __shared__ float s_sd[VB][456];    // 10 rows x (450 sd | 3 vt | pad)
    __shared__ float s_jr[NJ][VB];
    __shared__ float s_pd[NPOSE][32];  // 36 k-rows x 30 n-values (+pad)
    int tid = threadIdx.x;
    int v0 = blockIdx.x * VB;
    int slot = blockIdx.x & (NSLOT - 1);

    for (int i = tid; i < NJ * VB; i += 256) {
        int j = i / VB, vv = i % VB;
        int v = v0 + vv;
        s_jr[j][vv] = (v < VNUM) ? Jreg[j * VNUM + v] : 0.f;
    }
    // stage 10 sd rows (+vt) coalesced; zero beyond VNUM
    for (int i = tid; i < VB * 456; i += 256) {
        int r = i / 456, c = i - r * 456;
        int v = v0 + r;
        float val = 0.f;
        if (v < VNUM) {
            if (c < 450)      val = sd[v * 450 + c];
            else if (c < 453) val = vt[v * 3 + (c - 450)];
        }
        s_sd[r][c] = val;
    }
    // stage pd slice: row k, lane nn -> pd[k*PD_N + v0*3 + nn]  (coalesced)
    for (int i = tid; i < NPOSE * 32; i += 256) {
        int k = i >> 5, nn = i & 31;
        int ng = v0 * 3 + nn;
        s_pd[k][nn] = (nn < 30 && ng < PD_N) ? pd[(size_t)k * PD_N + ng] : 0.f;
    }
    __syncthreads();

    // --- Jr accumulation ---
    int col0 = tid, col1 = tid + 256;
    float acc[10];
#pragma unroll
    for (int q = 0; q < 10; q++) acc[q] = 0.f;
#pragma unroll
    for (int r = 0; r < VB; r++) {
        float j0 = s_jr[0][r], j1 = s_jr[1][r], j2 = s_jr[2][r];
        float j3 = s_jr[3][r], j4 = s_jr[4][r];
        float x0 = s_sd[r][col0];
        acc[0] = fmaf(j0, x0, acc[0]); acc[1] = fmaf(j1, x0, acc[1]);
        acc[2] = fmaf(j2, x0, acc[2]); acc[3] = fmaf(j3, x0, acc[3]);
        acc[4] = fmaf(j4, x0, acc[4]);
        if (col1 < JR_COLS) {
            float x1 = s_sd[r][col1];
            acc[5] = fmaf(j0, x1, acc[5]); acc[6] = fmaf(j1, x1, acc[6]);
            acc[7] = fmaf(j2, x1, acc[7]); acc[8] = fmaf(j3, x1, acc[8]);
            acc[9] = fmaf(j4, x1, acc[9]);
        }
    }

    // --- B3 build: 30 rows (n = 3v+c) x 96 bf16x2 (packed STG.32) ---
    for (int i = tid; i < 30 * 96; i += 256) {
        int nl = i / 96;
        int kk = (i - nl * 96) * 2;
        int n = v0 * 3 + nl;
        if (n < NPAD3) {
            int vl2 = nl / 3, c = nl - vl2 * 3;
            float f0 = 0.f, f1 = 0.f;
            if (kk < NBETA) {
                f0 = s_sd[vl2][c * NBETA + kk];
                f1 = s_sd[vl2][c * NBETA + kk + 1];
            } else if (kk < NBETA + NPOSE) {
                f0 = s_pd[kk - NBETA][nl];
                f1 = (kk + 1 < NBETA + NPOSE) ? s_pd[kk + 1 - NBETA][nl] : 0.f;
            }
            __nv_bfloat162 pk;
            pk.x = __float2bfloat16(f0);
            pk.y = __float2bfloat16(f1);
            *(__nv_bfloat162*)(g_B3 + (size_t)n * KP + kk) = pk;
        }
    }

    // --- atomics into slot (63 CTAs per address) ---
    float* jr = g_Jr8 + slot * NJ * JR_COLS;
#pragma unroll
    for (int j = 0; j < NJ; j++) {
        atomicAdd(&jr[j * JR_COLS + col0], acc[j]);
        if (col1 < JR_COLS) atomicAdd(&jr[j * JR_COLS + col1], acc[5 + j]);
    }
}

// ============================================================
// Launch 2 — kernB: joints, Rodrigues, chain -> g_relT + bf16 A rows.
// 32 blocks x 32 threads (1 batch/thread).  Sums the 8 Jr slots.
// ============================================================
#define BP 153

__global__ void __launch_bounds__(32) kernB(
    const float* __restrict__ shape, const float* __restrict__ expr,
    const float* __restrict__ pose, const float* __restrict__ eye,
    const float* __restrict__ neck)
{
    __shared__ float s_jr[NJ * JR_COLS];
    __shared__ float s_beta[32 * BP];
    int tid = threadIdx.x;
    int b0 = blockIdx.x * 32;

    for (int i = tid; i < NJ * JR_COLS; i += 32) {
        float s = 0.f;
#pragma unroll
        for (int t = 0; t < NSLOT; t++) s += g_Jr8[t * NJ * JR_COLS + i];
        s_jr[i] = s;
    }
    for (int i = tid; i < 32 * NSHAPE; i += 32)
        s_beta[(i / NSHAPE) * BP + (i % NSHAPE)] = shape[b0 * NSHAPE + i];
    for (int i = tid; i < 32 * NEXPR; i += 32)
        s_beta[(i / NEXPR) * BP + NSHAPE + (i % NEXPR)] = expr[b0 * NEXPR + i];
    __syncthreads();

    int b = b0 + tid;
    const float* myb = s_beta + tid * BP;

    float J[NJ][3];
#pragma unroll
    for (int j = 0; j < NJ; j++)
#pragma unroll
        for (int c = 0; c < 3; c++) J[j][c] = s_jr[j * JR_COLS + 450 + c];

    for (int l = 0; l < NBETA; l++) {
        float blv = myb[l];
#pragma unroll
        for (int j = 0; j < NJ; j++)
#pragma unroll
            for (int c = 0; c < 3; c++) J[j][c] = fmaf(s_jr[j * JR_COLS + l], blv, J[j][c]);
    }

    float fp[15];
    fp[0] = pose[b * 6 + 0]; fp[1] = pose[b * 6 + 1]; fp[2] = pose[b * 6 + 2];
    fp[3] = neck[0]; fp[4] = neck[1]; fp[5] = neck[2];
    fp[6] = pose[b * 6 + 3]; fp[7] = pose[b * 6 + 4]; fp[8] = pose[b * 6 + 5];
#pragma unroll
    for (int k = 0; k < 6; k++) fp[9 + k] = eye[k];

    float R[NJ][9];
#pragma unroll
    for (int j = 0; j < NJ; j++) {
        float x = fp[j * 3 + 0], y = fp[j * 3 + 1], z = fp[j * 3 + 2];
        float xa = x + 1e-8f, ya = y + 1e-8f, za = z + 1e-8f;
        float ang = sqrtf(xa * xa + ya * ya + za * za);
        float inv = 1.f / ang;
        float rx = x * inv, ry = y * inv, rz = z * inv;
        float s, c;
        sincosf(ang, &s, &c);
        float t = 1.f - c;
        R[j][0] = 1.f - t * (ry * ry + rz * rz);
        R[j][1] = -s * rz + t * rx * ry;
        R[j][2] =  s * ry + t * rx * rz;
        R[j][3] =  s * rz + t * rx * ry;
        R[j][4] = 1.f - t * (rx * rx + rz * rz);
        R[j][5] = -s * rx + t * ry * rz;
        R[j][6] = -s * ry + t * rx * rz;
        R[j][7] =  s * rx + t * ry * rz;
        R[j][8] = 1.f - t * (rx * rx + ry * ry);
    }

    // --- g_A row: [betas(150) | pose_feature(36) | 0 pad(6)] bf16 ---
    {
        __nv_bfloat16* arow = g_A + (size_t)b * KP;
#pragma unroll 2
        for (int l = 0; l < NBETA; l++) arow[l] = __float2bfloat16(myb[l]);
#pragma unroll
        for (int j = 1; j < NJ; j++)
#pragma unroll
            for (int k = 0; k < 9; k++) {
                float d = (k == 0 || k == 4 || k == 8) ? 1.f : 0.f;
                arow[NBETA + (j - 1) * 9 + k] = __float2bfloat16(R[j][k] - d);
            }
#pragma unroll
        for (int k = NBETA + NPOSE; k < KP; k++) arow[k] = __float2bfloat16(0.f);
    }

    const int par[NJ] = { -1, 0, 1, 1, 1 };
    float rel[NJ][3];
#pragma unroll
    for (int c = 0; c < 3; c++) rel[0][c] = J[0][c];
#pragma unroll
    for (int j = 1; j < NJ; j++)
#pragma unroll
        for (int c = 0; c < 3; c++) rel[j][c] = J[j][c] - J[par[j]][c];

    float cR[NJ][9], ct[NJ][3];
#pragma unroll
    for (int k = 0; k < 9; k++) cR[0][k] = R[0][k];
#pragma unroll
    for (int c = 0; c < 3; c++) ct[0][c] = rel[0][c];
#pragma unroll
    for (int j = 1; j < NJ; j++) {
        int p = par[j];
#pragma unroll
        for (int r = 0; r < 3; r++) {
#pragma unroll
            for (int c = 0; c < 3; c++)
                cR[j][r * 3 + c] = cR[p][r * 3 + 0] * R[j][0 + c]
                                 + cR[p][r * 3 + 1] * R[j][3 + c]
                                 + cR[p][r * 3 + 2] * R[j][6 + c];
            ct[j][r] = cR[p][r * 3 + 0] * rel[j][0] + cR[p][r * 3 + 1] * rel[j][1]
                     + cR[p][r * 3 + 2] * rel[j][2] + ct[p][r];
        }
    }

#pragma unroll
    for (int j = 0; j < NJ; j++)
#pragma unroll
        for (int r = 0; r < 3; r++) {
            float tr = ct[j][r] - (cR[j][r * 3 + 0] * J[j][0] + cR[j][r * 3 + 1] * J[j][1]
                                 + cR[j][r * 3 + 2] * J[j][2]);
            g_relT[b * 60 + j * 12 + r * 4 + 0] = cR[j][r * 3 + 0];
            g_relT[b * 60 + j * 12 + r * 4 + 1] = cR[j][r * 3 + 1];
            g_relT[b * 60 + j * 12 + r * 4 + 2] = cR[j][r * 3 + 2];
            g_relT[b * 60 + j * 12 + r * 4 + 3] = tr;
        }
}

// ============================================================
// Launch 3 — kernG: C[64b x 192n] = A @ B3^T (mma.sync bf16)
// + fused LBS epilogue.  Natural n = 3v+c layout (no pad column):
// 25% fewer HMMAs than the pad-4 layout.
// 256 thr = 8 warps (2m x 4n), warp tile 32b x 48n
// (2 A-frags + 3 B-frags = 5 LDSM -> 12 MMA, ratio 2.4), 2 CTAs/SM.
// smem mainloop: A@0 (64x400B=25600), B@25600 (192x400B=76800) -> 102400
// epilogue reuse: sC@0 (64x196 f32=50176), relT@50176 (15360),
//                 wvt@65536 (64x8 f32=2048)
// ============================================================
#define SMB_OFF 25600
#define SM_TOT  102400

__global__ void __launch_bounds__(256, 2) kernG(
    const float* __restrict__ vt, const float* __restrict__ lw,
    float* __restrict__ out)
{
    extern __shared__ char smr[];
    uint32_t sb = smem_u32(smr);
    int tid = threadIdx.x;
    int lane = tid & 31, w = tid >> 5;
    int wm = w & 1, wn = w >> 1;          // 2 m-warps x 4 n-warps; warp tile 32x48
    int n0 = blockIdx.x * 192;
    int b0 = blockIdx.y * 64;
    int v0 = blockIdx.x * 64;             // 64 vertices per tile

    // --- stage A (64x24 uint4) + B (192x24 uint4) via cp.async, pitch 400B ---
    {
        const uint4* gA4 = (const uint4*)(g_A + (size_t)b0 * KP);
        const uint4* gB4 = (const uint4*)(g_B3 + (size_t)n0 * KP);
        for (int i = tid; i < 64 * 24; i += 256) {
            int row = i / 24, q = i - row * 24;
            CP_ASYNC16(sb + row * 400 + q * 16, gA4 + i);
        }
        for (int i = tid; i < 192 * 24; i += 256) {
            int row = i / 24, q = i - row * 24;
            CP_ASYNC16(sb + SMB_OFF + row * 400 + q * 16, gB4 + i);
        }
        CP_ASYNC_WAIT();
    }
    __syncthreads();

    float acc[2][6][4];
#pragma unroll
    for (int a = 0; a < 2; a++)
#pragma unroll
        for (int j = 0; j < 6; j++)
#pragma unroll
            for (int k = 0; k < 4; k++) acc[a][j][k] = 0.f;

    int lrow = lane & 15;
    uint32_t koff = (uint32_t)((lane >> 4) * 16);
    uint32_t aBase = sb + (wm * 32 + lrow) * 400 + koff;
    uint32_t bBase = sb + SMB_OFF + (wn * 48 + lrow) * 400 + koff;

#pragma unroll
    for (int ks = 0; ks < 12; ks++) {
        uint32_t kb = (uint32_t)ks * 32u;
        uint32_t ra[2][4], rb[3][4];
        LDSM4(ra[0][0], ra[0][1], ra[0][2], ra[0][3], aBase + kb);
        LDSM4(ra[1][0], ra[1][1], ra[1][2], ra[1][3], aBase + 16 * 400 + kb);
#pragma unroll
        for (int jj = 0; jj < 3; jj++)
            LDSM4(rb[jj][0], rb[jj][1], rb[jj][2], rb[jj][3], bBase + jj * (16 * 400) + kb);
#pragma unroll
        for (int a = 0; a < 2; a++)
#pragma unroll
            for (int jj = 0; jj < 3; jj++) {
                MMA16816(acc[a][jj * 2],     ra[a][0], ra[a][1], ra[a][2], ra[a][3],
                         rb[jj][0], rb[jj][2]);
                MMA16816(acc[a][jj * 2 + 1], ra[a][0], ra[a][1], ra[a][2], ra[a][3],
                         rb[jj][1], rb[jj][3]);
            }
    }

    __syncthreads();   // done reading A/B smem

    // --- write accumulators to sC [64 x 196] f32 ---
    float* sC = (float*)smr;
#pragma unroll
    for (int a = 0; a < 2; a++) {
        int r = wm * 32 + a * 16 + (lane >> 2);
        int cl = (lane & 3) * 2;
#pragma unroll
        for (int j6 = 0; j6 < 6; j6++) {
            int jj = j6 >> 1, h = j6 & 1;
            int c = wn * 48 + jj * 16 + h * 8 + cl;
            sC[r * 196 + c]           = acc[a][j6][0];
            sC[r * 196 + c + 1]       = acc[a][j6][1];
            sC[(r + 8) * 196 + c]     = acc[a][j6][2];
            sC[(r + 8) * 196 + c + 1] = acc[a][j6][3];
        }
    }

    // --- stage relT (64x60) and packed weights+template (64x8) ---
    float* sRT = (float*)(smr + 50176);
    for (int i = tid; i < 64 * 60; i += 256) sRT[i] = g_relT[b0 * 60 + i];
    float* sWVT = (float*)(smr + 65536);
    for (int i = tid; i < 64 * 8; i += 256) {
        int vl = i >> 3, q = i & 7;
        int v = v0 + vl;
        float val = 0.f;
        if (v < VNUM) {
            if (q < 5)      val = lw[v * NJ + q];
            else if (q < 8) val = vt[v * 3 + (q - 5)];
        }
        sWVT[i] = val;
    }
    __syncthreads();

    // --- epilogue: fixed vertex per thread (vl = tid&63); 16 bl each ---
    {
        int vl = tid & 63;
        int g = tid >> 6;                  // 0..3, warp-uniform
        int v = v0 + vl;
        bool ok = (v < VNUM);
        int vl3 = vl * 3;
        float w0 = sWVT[vl * 8 + 0], w1 = sWVT[vl * 8 + 1], w2 = sWVT[vl * 8 + 2];
        float w3 = sWVT[vl * 8 + 3], w4 = sWVT[vl * 8 + 4];
        float vtx = sWVT[vl * 8 + 5], vty = sWVT[vl * 8 + 6], vtz = sWVT[vl * 8 + 7];

#pragma unroll 4
        for (int it = 0; it < 16; it++) {
            int bl = it * 4 + g;           // warp-uniform batch row
            const float* cr = sC + bl * 196 + vl3;
            float cx = cr[0], cy = cr[1], cz = cr[2];
            const float4* rt4 = (const float4*)(sRT + bl * 60);   // broadcast
            float4 T4[3];
#pragma unroll
            for (int q = 0; q < 3; q++) {
                float4 r0 = rt4[q], r1 = rt4[3 + q], r2 = rt4[6 + q];
                float4 r3 = rt4[9 + q], r4 = rt4[12 + q];
                T4[q].x = fmaf(w0, r0.x, fmaf(w1, r1.x, fmaf(w2, r2.x, fmaf(w3, r3.x, w4 * r4.x))));
                T4[q].y = fmaf(w0, r0.y, fmaf(w1, r1.y, fmaf(w2, r2.y, fmaf(w3, r3.y, w4 * r4.y))));
                T4[q].z = fmaf(w0, r0.z, fmaf(w1, r1.z, fmaf(w2, r2.z, fmaf(w3, r3.z, w4 * r4.z))));
                T4[q].w = fmaf(w0, r0.w, fmaf(w1, r1.w, fmaf(w2, r2.w, fmaf(w3, r3.w, w4 * r4.w))));
            }
            float px = cx + vtx;
            float py = cy + vty;
            float pz = cz + vtz;
            float ox = fmaf(T4[0].x, px, fmaf(T4[0].y, py, fmaf(T4[0].z, pz, T4[0].w)));
            float oy = fmaf(T4[1].x, px, fmaf(T4[1].y, py, fmaf(T4[1].z, pz, T4[1].w)));
            float oz = fmaf(T4[2].x, px, fmaf(T4[2].y, py, fmaf(T4[2].z, pz, T4[2].w)));
            if (ok) {
                size_t base = ((size_t)(b0 + bl) * VNUM + v) * 3;
                out[base + 0] = ox; out[base + 1] = oy; out[base + 2] = oz;
            }
        }
    }
}

// ============================================================
// Launch 4 — kernD: landmark gather + Jr-slot re-zero (replaces kernZ;
// runs after kernB consumed the slots, restoring the zero invariant
// for the next graph replay).
// ============================================================
__global__ void kernD(const int* __restrict__ land, const float* __restrict__ verts,
                      float* __restrict__ lmk)
{
    if (blockIdx.x < NSLOT) {
        int base = blockIdx.x * NJ * JR_COLS;
        for (int i = threadIdx.x; i < NJ * JR_COLS; i += blockDim.x)
            g_Jr8[base + i] = 0.f;
    }
    int i = blockIdx.x * blockDim.x + threadIdx.x;
    if (i >= NB * NLMK) return;
    int b = i / NLMK, k = i % NLMK;
    int v = land[k];
    size_t src = ((size_t)b * VNUM + v) * 3;
    size_t dst = (size_t)i * 3;
    lmk[dst + 0] = verts[src + 0];
    lmk[dst + 1] = verts[src + 1];
    lmk[dst + 2] = verts[src + 2];
}

// ============================================================
extern "C" void kernel_launch(void* const* d_in, const int* in_sizes, int n_in,
                              void* d_out, int out_size)
{
    const float* shape = (const float*)d_in[0];
    const float* expr  = (const float*)d_in[1];
    const float* pose  = (const float*)d_in[2];
    const int*   land  = (const int*)  d_in[3];
    const float* vt    = (const float*)d_in[4];
    const float* sd    = (const float*)d_in[5];
    const float* pd    = (const float*)d_in[6];
    const float* Jreg  = (const float*)d_in[7];
    const float* lw    = (const float*)d_in[8];
    const float* eye   = (const float*)d_in[9];
    const float* neck  = (const float*)d_in[10];
    float* out = (float*)d_out;

    cudaFuncSetAttribute(kernG, cudaFuncAttributeMaxDynamicSharedMemorySize, SM_TOT);

    kernF1<<<F1_BLK, 256>>>(sd, vt, pd, Jreg);            // launch 1
    kernB<<<NB / 32, 32>>>(shape, expr, pose, eye, neck); // launch 2
    dim3 gg(NPAD3 / 192, NB / 64);
    kernG<<<gg, 256, SM_TOT>>>(vt, lw, out);              // launch 3
    float* lmk = out + (size_t)NB * VNUM * 3;
    kernD<<<(NB * NLMK + 255) / 256, 256>>>(land, out, lmk);  // launch 4
}

// round 15
// speedup vs baseline: 1.0773x; 1.0412x over previous
#include <cuda_runtime.h>
#include <cuda_bf16.h>
#include <math.h>
#include <stdint.h>

#define VNUM   5023
#define NJ     5
#define NB     1024
#define NSHAPE 100
#define NEXPR  50
#define NBETA  150
#define NLMK   68
#define NPOSE  36
#define JR_COLS 453
#define PD_N   (VNUM * 3)      // 15069

#define KP    192              // padded K: 150 betas + 36 pose feats + 6 zero
#define NPAD4 20096            // 157 * 128 >= 4*VNUM

#define VB      10             // vertices per F1 block
#define F1_BLK  504            // 504*10 = 5040 >= 5023
#define NSLOT   8              // Jr accumulator slots (atomic contention split)

// ---- device scratch ----
__device__ float g_Jr8[NSLOT * NJ * JR_COLS];         // zero at load; kernD re-zeros
__device__ float g_relT[NB * NJ * 12];
__device__ __nv_bfloat16 g_A[NB * KP];                // 0.4 MB
__device__ __nv_bfloat16 g_B4[(size_t)NPAD4 * KP];    // 7.7 MB (c==3 rows stay 0)

__device__ __forceinline__ uint32_t smem_u32(const void* p) {
    uint32_t a;
    asm("{ .reg .u64 t; cvta.to.shared.u64 t, %1; cvt.u32.u64 %0, t; }" : "=r"(a) : "l"(p));
    return a;
}

#define LDSM4(R0, R1, R2, R3, ADDR) \
    asm volatile("ldmatrix.sync.aligned.m8n8.x4.shared.b16 {%0,%1,%2,%3}, [%4];" \
        : "=r"(R0), "=r"(R1), "=r"(R2), "=r"(R3) : "r"(ADDR))

#define MMA16816(C, A0, A1, A2, A3, B0, B1) \
    asm volatile("mma.sync.aligned.m16n8k16.row.col.f32.bf16.bf16.f32 " \
        "{%0,%1,%2,%3},{%4,%5,%6,%7},{%8,%9},{%0,%1,%2,%3};" \
        : "+f"((C)[0]), "+f"((C)[1]), "+f"((C)[2]), "+f"((C)[3]) \
        : "r"(A0), "r"(A1), "r"(A2), "r"(A3), "r"(B0), "r"(B1))

#define CP_ASYNC16(DST, SRC) \
    asm volatile("cp.async.cg.shared.global [%0], [%1], 16;" :: "r"(DST), "l"(SRC))
#define CP_ASYNC_WAIT() \
    asm volatile("cp.async.commit_group;\n\tcp.async.wait_group 0;" ::: "memory")

// ============================================================
// Launch 1 — kernF1: fused B4 build + Jr accumulation.
// 504 blocks x 256 threads; each block owns 10 vertices.
// sd rows staged once (used for Jr AND B4); pd slice staged coalesced.
// B4 stores packed bf16x2 (STG.32); c==3 pad rows are never written
// (load-time zero, deterministic). Atomics into slot blockIdx&7;
// slots zeroed by the previous replay's kernD.
// ============================================================
__global__ void __launch_bounds__(256) kernF1(
    const float* __restrict__ sd, const float* __restrict__ vt,
    const float* __restrict__ pd, const float* __restrict__ Jreg)
{
    __shared__ float s_sd[VB][456];    // 10 rows x (450 sd | 3 vt | pad)
    __shared__ float s_jr[NJ][VB];
    __shared__ float s_pd[NPOSE][32];  // 36 k-rows x 30 n-values (+pad)
    int tid = threadIdx.x;
    int v0 = blockIdx.x * VB;
    int slot = blockIdx.x & (NSLOT - 1);

    for (int i = tid; i < NJ * VB; i += 256) {
        int j = i / VB, vv = i % VB;
        int v = v0 + vv;
        s_jr[j][vv] = (v < VNUM) ? Jreg[j * VNUM + v] : 0.f;
    }
    // stage 10 sd rows (+vt) coalesced; zero beyond VNUM
    for (int i = tid; i < VB * 456; i += 256) {
        int r = i / 456, c = i - r * 456;
        int v = v0 + r;
        float val = 0.f;
        if (v < VNUM) {
            if (c < 450)      val = sd[v * 450 + c];
            else if (c < 453) val = vt[v * 3 + (c - 450)];
        }
        s_sd[r][c] = val;
    }
    // stage pd slice: row k, lane nn -> pd[k*PD_N + v0*3 + nn]  (coalesced)
    for (int i = tid; i < NPOSE * 32; i += 256) {
        int k = i >> 5, nn = i & 31;
        int ng = v0 * 3 + nn;
        s_pd[k][nn] = (nn < 30 && ng < PD_N) ? pd[(size_t)k * PD_N + ng] : 0.f;
    }
    __syncthreads();

    // --- Jr accumulation ---
    int col0 = tid, col1 = tid + 256;
    float acc[10];
#pragma unroll
    for (int q = 0; q < 10; q++) acc[q] = 0.f;
#pragma unroll
    for (int r = 0; r < VB; r++) {
        float j0 = s_jr[0][r], j1 = s_jr[1][r], j2 = s_jr[2][r];
        float j3 = s_jr[3][r], j4 = s_jr[4][r];
        float x0 = s_sd[r][col0];
        acc[0] = fmaf(j0, x0, acc[0]); acc[1] = fmaf(j1, x0, acc[1]);
        acc[2] = fmaf(j2, x0, acc[2]); acc[3] = fmaf(j3, x0, acc[3]);
        acc[4] = fmaf(j4, x0, acc[4]);
        if (col1 < JR_COLS) {
            float x1 = s_sd[r][col1];
            acc[5] = fmaf(j0, x1, acc[5]); acc[6] = fmaf(j1, x1, acc[6]);
            acc[7] = fmaf(j2, x1, acc[7]); acc[8] = fmaf(j3, x1, acc[8]);
            acc[9] = fmaf(j4, x1, acc[9]);
        }
    }

    // --- B4 build: only the 30 real rows (c < 3); c==3 rows stay zero ---
    // nl indexes (vl2, c) with c in 0..2; global row n = (v0+vl2)*4 + c.
    for (int i = tid; i < 30 * 96; i += 256) {
        int nl = i / 96;
        int kk = (i - nl * 96) * 2;
        int vl2 = nl / 3, c = nl - vl2 * 3;
        int n = (v0 + vl2) * 4 + c;
        if (n < NPAD4) {
            float f0 = 0.f, f1 = 0.f;
            if (kk < NBETA) {
                f0 = s_sd[vl2][c * NBETA + kk];
                f1 = s_sd[vl2][c * NBETA + kk + 1];
            } else if (kk < NBETA + NPOSE) {
                f0 = s_pd[kk - NBETA][vl2 * 3 + c];
                f1 = (kk + 1 < NBETA + NPOSE) ? s_pd[kk + 1 - NBETA][vl2 * 3 + c] : 0.f;
            }
            __nv_bfloat162 pk;
            pk.x = __float2bfloat16(f0);
            pk.y = __float2bfloat16(f1);
            *(__nv_bfloat162*)(g_B4 + (size_t)n * KP + kk) = pk;
        }
    }

    // --- atomics into slot (63 CTAs per address) ---
    float* jr = g_Jr8 + slot * NJ * JR_COLS;
#pragma unroll
    for (int j = 0; j < NJ; j++) {
        atomicAdd(&jr[j * JR_COLS + col0], acc[j]);
        if (col1 < JR_COLS) atomicAdd(&jr[j * JR_COLS + col1], acc[5 + j]);
    }
}

// ============================================================
// Launch 2 — kernB: joints, Rodrigues, chain -> g_relT + bf16 A rows.
// 32 blocks x 32 threads (1 batch/thread).  Sums the 8 Jr slots.
// ============================================================
#define BP 153

__global__ void __launch_bounds__(32) kernB(
    const float* __restrict__ shape, const float* __restrict__ expr,
    const float* __restrict__ pose, const float* __restrict__ eye,
    const float* __restrict__ neck)
{
    __shared__ float s_jr[NJ * JR_COLS];
    __shared__ float s_beta[32 * BP];
    int tid = threadIdx.x;
    int b0 = blockIdx.x * 32;

    for (int i = tid; i < NJ * JR_COLS; i += 32) {
        float s = 0.f;
#pragma unroll
        for (int t = 0; t < NSLOT; t++) s += g_Jr8[t * NJ * JR_COLS + i];
        s_jr[i] = s;
    }
    for (int i = tid; i < 32 * NSHAPE; i += 32)
        s_beta[(i / NSHAPE) * BP + (i % NSHAPE)] = shape[b0 * NSHAPE + i];
    for (int i = tid; i < 32 * NEXPR; i += 32)
        s_beta[(i / NEXPR) * BP + NSHAPE + (i % NEXPR)] = expr[b0 * NEXPR + i];
    __syncthreads();

    int b = b0 + tid;
    const float* myb = s_beta + tid * BP;

    float J[NJ][3];
#pragma unroll
    for (int j = 0; j < NJ; j++)
#pragma unroll
        for (int c = 0; c < 3; c++) J[j][c] = s_jr[j * JR_COLS + 450 + c];

    for (int l = 0; l < NBETA; l++) {
        float blv = myb[l];
#pragma unroll
        for (int j = 0; j < NJ; j++)
#pragma unroll
            for (int c = 0; c < 3; c++) J[j][c] = fmaf(s_jr[j * JR_COLS + l], blv, J[j][c]);
    }

    float fp[15];
    fp[0] = pose[b * 6 + 0]; fp[1] = pose[b * 6 + 1]; fp[2] = pose[b * 6 + 2];
    fp[3] = neck[0]; fp[4] = neck[1]; fp[5] = neck[2];
    fp[6] = pose[b * 6 + 3]; fp[7] = pose[b * 6 + 4]; fp[8] = pose[b * 6 + 5];
#pragma unroll
    for (int k = 0; k < 6; k++) fp[9 + k] = eye[k];

    float R[NJ][9];
#pragma unroll
    for (int j = 0; j < NJ; j++) {
        float x = fp[j * 3 + 0], y = fp[j * 3 + 1], z = fp[j * 3 + 2];
        float xa = x + 1e-8f, ya = y + 1e-8f, za = z + 1e-8f;
        float ang = sqrtf(xa * xa + ya * ya + za * za);
        float inv = 1.f / ang;
        float rx = x * inv, ry = y * inv, rz = z * inv;
        float s, c;
        sincosf(ang, &s, &c);
        float t = 1.f - c;
        R[j][0] = 1.f - t * (ry * ry + rz * rz);
        R[j][1] = -s * rz + t * rx * ry;
        R[j][2] =  s * ry + t * rx * rz;
        R[j][3] =  s * rz + t * rx * ry;
        R[j][4] = 1.f - t * (rx * rx + rz * rz);
        R[j][5] = -s * rx + t * ry * rz;
        R[j][6] = -s * ry + t * rx * rz;
        R[j][7] =  s * rx + t * ry * rz;
        R[j][8] = 1.f - t * (rx * rx + ry * ry);
    }

    // --- g_A row: [betas(150) | pose_feature(36) | 0 pad(6)] bf16 ---
    {
        __nv_bfloat16* arow = g_A + (size_t)b * KP;
#pragma unroll 2
        for (int l = 0; l < NBETA; l++) arow[l] = __float2bfloat16(myb[l]);
#pragma unroll
        for (int j = 1; j < NJ; j++)
#pragma unroll
            for (int k = 0; k < 9; k++) {
                float d = (k == 0 || k == 4 || k == 8) ? 1.f : 0.f;
                arow[NBETA + (j - 1) * 9 + k] = __float2bfloat16(R[j][k] - d);
            }
#pragma unroll
        for (int k = NBETA + NPOSE; k < KP; k++) arow[k] = __float2bfloat16(0.f);
    }

    const int par[NJ] = { -1, 0, 1, 1, 1 };
    float rel[NJ][3];
#pragma unroll
    for (int c = 0; c < 3; c++) rel[0][c] = J[0][c];
#pragma unroll
    for (int j = 1; j < NJ; j++)
#pragma unroll
        for (int c = 0; c < 3; c++) rel[j][c] = J[j][c] - J[par[j]][c];

    float cR[NJ][9], ct[NJ][3];
#pragma unroll
    for (int k = 0; k < 9; k++) cR[0][k] = R[0][k];
#pragma unroll
    for (int c = 0; c < 3; c++) ct[0][c] = rel[0][c];
#pragma unroll
    for (int j = 1; j < NJ; j++) {
        int p = par[j];
#pragma unroll
        for (int r = 0; r < 3; r++) {
#pragma unroll
            for (int c = 0; c < 3; c++)
                cR[j][r * 3 + c] = cR[p][r * 3 + 0] * R[j][0 + c]
                                 + cR[p][r * 3 + 1] * R[j][3 + c]
                                 + cR[p][r * 3 + 2] * R[j][6 + c];
            ct[j][r] = cR[p][r * 3 + 0] * rel[j][0] + cR[p][r * 3 + 1] * rel[j][1]
                     + cR[p][r * 3 + 2] * rel[j][2] + ct[p][r];
        }
    }

#pragma unroll
    for (int j = 0; j < NJ; j++)
#pragma unroll
        for (int r = 0; r < 3; r++) {
            float tr = ct[j][r] - (cR[j][r * 3 + 0] * J[j][0] + cR[j][r * 3 + 1] * J[j][1]
                                 + cR[j][r * 3 + 2] * J[j][2]);
            g_relT[b * 60 + j * 12 + r * 4 + 0] = cR[j][r * 3 + 0];
            g_relT[b * 60 + j * 12 + r * 4 + 1] = cR[j][r * 3 + 1];
            g_relT[b * 60 + j * 12 + r * 4 + 2] = cR[j][r * 3 + 2];
            g_relT[b * 60 + j * 12 + r * 4 + 3] = tr;
        }
}

// ============================================================
// Launch 3 — kernG: C[128b x 64n] = A @ B4^T (mma.sync bf16)
// + fused LBS epilogue.  (R11-measured version: 69.2us)
// 256 thr = 8 warps (4b x 2n), warp tile 32b x 32n, 3 CTAs/SM.
// smem mainloop: A@0 (128x400B=51200), B@51200 (64x400B=25600) -> 76800
// epilogue reuse: sC@0 (128x68 f32=34816), relT@34816 (30720),
//                 w@65536 (320), vt@65856 (192)
// ============================================================
#define SMB_OFF 51200
#define SM_TOT  76800

__global__ void __launch_bounds__(256, 3) kernG(
    const float* __restrict__ vt, const float* __restrict__ lw,
    float* __restrict__ out)
{
    extern __shared__ char smr[];
    uint32_t sb = smem_u32(smr);
    int tid = threadIdx.x;
    int lane = tid & 31, w = tid >> 5;
    int wm = w & 3, wn = w >> 2;          // 4b x 2n grid, warp tile 32b x 32n
    int n0 = blockIdx.x * 64;
    int b0 = blockIdx.y * 128;
    int v0 = n0 >> 2;                     // 16 vertices per tile

    // --- stage A (128x24 uint4) + B (64x24 uint4) via cp.async, pitch 400B ---
    {
        const uint4* gA4 = (const uint4*)(g_A + (size_t)b0 * KP);
        const uint4* gB4 = (const uint4*)(g_B4 + (size_t)n0 * KP);
        for (int i = tid; i < 128 * 24; i += 256) {
            int row = i / 24, q = i - row * 24;
            CP_ASYNC16(sb + row * 400 + q * 16, gA4 + i);
        }
        for (int i = tid; i < 64 * 24; i += 256) {
            int row = i / 24, q = i - row * 24;
            CP_ASYNC16(sb + SMB_OFF + row * 400 + q * 16, gB4 + i);
        }
        CP_ASYNC_WAIT();
    }
    __syncthreads();

    float acc[2][4][4];
#pragma unroll
    for (int a = 0; a < 2; a++)
#pragma unroll
        for (int j = 0; j < 4; j++)
#pragma unroll
            for (int k = 0; k < 4; k++) acc[a][j][k] = 0.f;

    int lrow = lane & 15;
    uint32_t koff = (uint32_t)((lane >> 4) * 16);
    uint32_t aBase = sb + (wm * 32 + lrow) * 400 + koff;
    uint32_t bBase = sb + SMB_OFF + (wn * 32 + lrow) * 400 + koff;

#pragma unroll
    for (int ks = 0; ks < 12; ks++) {
        uint32_t kb = (uint32_t)ks * 32u;
        uint32_t ra[2][4], rb[2][4];
        LDSM4(ra[0][0], ra[0][1], ra[0][2], ra[0][3], aBase + kb);
        LDSM4(ra[1][0], ra[1][1], ra[1][2], ra[1][3], aBase + 16 * 400 + kb);
        LDSM4(rb[0][0], rb[0][1], rb[0][2], rb[0][3], bBase + kb);
        LDSM4(rb[1][0], rb[1][1], rb[1][2], rb[1][3], bBase + 16 * 400 + kb);
#pragma unroll
        for (int a = 0; a < 2; a++)
#pragma unroll
            for (int jj = 0; jj < 2; jj++) {
                MMA16816(acc[a][jj * 2],     ra[a][0], ra[a][1], ra[a][2], ra[a][3],
                         rb[jj][0], rb[jj][2]);
                MMA16816(acc[a][jj * 2 + 1], ra[a][0], ra[a][1], ra[a][2], ra[a][3],
                         rb[jj][1], rb[jj][3]);
            }
    }

    __syncthreads();   // done reading A/B smem

    // --- write accumulators to sC [128 x 68] f32 ---
    float* sC = (float*)smr;
#pragma unroll
    for (int a = 0; a < 2; a++) {
        int r = wm * 32 + a * 16 + (lane >> 2);
        int cb = wn * 32 + (lane & 3) * 2;
#pragma unroll
        for (int j = 0; j < 4; j++) {
            int c = cb + j * 8;
            sC[r * 68 + c]           = acc[a][j][0];
            sC[r * 68 + c + 1]       = acc[a][j][1];
            sC[(r + 8) * 68 + c]     = acc[a][j][2];
            sC[(r + 8) * 68 + c + 1] = acc[a][j][3];
        }
    }

    // --- stage relT / weights / template ---
    float* sRT = (float*)(smr + 34816);
    for (int i = tid; i < 128 * 60; i += 256) sRT[i] = g_relT[b0 * 60 + i];
    float* sW = (float*)(smr + 65536);
    if (tid < 16 * NJ) {
        int vl = tid / NJ;
        int v = v0 + vl;
        sW[tid] = (v < VNUM) ? lw[v * NJ + (tid % NJ)] : 0.f;
    }
    float* sVT = (float*)(smr + 65856);
    if (tid < 48) {
        int vl = tid / 3;
        int v = v0 + vl;
        sVT[tid] = (v < VNUM) ? vt[v * 3 + (tid % 3)] : 0.f;
    }
    __syncthreads();

    // --- per (b, v): blend transform (float4 vectorized), apply, store ---
#pragma unroll 4
    for (int it = 0; it < 8; it++) {
        int p = it * 256 + tid;
        int vl = p & 15, bl = p >> 4;
        int v = v0 + vl;
        float4 cv = *(const float4*)(sC + bl * 68 + vl * 4);
        const float4* rt4 = (const float4*)(sRT + bl * 60);   // 15 float4
        float w0 = sW[vl * NJ + 0], w1 = sW[vl * NJ + 1], w2 = sW[vl * NJ + 2];
        float w3 = sW[vl * NJ + 3], w4 = sW[vl * NJ + 4];
        float4 T4[3];
#pragma unroll
        for (int q = 0; q < 3; q++) {
            float4 r0 = rt4[q], r1 = rt4[3 + q], r2 = rt4[6 + q];
            float4 r3 = rt4[9 + q], r4 = rt4[12 + q];
            T4[q].x = fmaf(w0, r0.x, fmaf(w1, r1.x, fmaf(w2, r2.x, fmaf(w3, r3.x, w4 * r4.x))));
            T4[q].y = fmaf(w0, r0.y, fmaf(w1, r1.y, fmaf(w2, r2.y, fmaf(w3, r3.y, w4 * r4.y))));
            T4[q].z = fmaf(w0, r0.z, fmaf(w1, r1.z, fmaf(w2, r2.z, fmaf(w3, r3.z, w4 * r4.z))));
            T4[q].w = fmaf(w0, r0.w, fmaf(w1, r1.w, fmaf(w2, r2.w, fmaf(w3, r3.w, w4 * r4.w))));
        }
        float px = cv.x + sVT[vl * 3 + 0];
        float py = cv.y + sVT[vl * 3 + 1];
        float pz = cv.z + sVT[vl * 3 + 2];
        float ox = fmaf(T4[0].x, px, fmaf(T4[0].y, py, fmaf(T4[0].z, pz, T4[0].w)));
        float oy = fmaf(T4[1].x, px, fmaf(T4[1].y, py, fmaf(T4[1].z, pz, T4[1].w)));
        float oz = fmaf(T4[2].x, px, fmaf(T4[2].y, py, fmaf(T4[2].z, pz, T4[2].w)));
        if (v < VNUM) {
            size_t base = ((size_t)(b0 + bl) * VNUM + v) * 3;
            out[base + 0] = ox; out[base + 1] = oy; out[base + 2] = oz;
        }
    }
}

// ============================================================
// Launch 4 — kernD: landmark gather + Jr-slot re-zero (runs after
// kernB consumed the slots; restores the zero invariant for the
// next graph replay; load-time zero covers the very first call).
// ============================================================
__global__ void kernD(const int* __restrict__ land, const float* __restrict__ verts,
                      float* __restrict__ lmk)
{
    if (blockIdx.x < NSLOT) {
        int base = blockIdx.x * NJ * JR_COLS;
        for (int i = threadIdx.x; i < NJ * JR_COLS; i += blockDim.x)
            g_Jr8[base + i] = 0.f;
    }
    int i = blockIdx.x * blockDim.x + threadIdx.x;
    if (i >= NB * NLMK) return;
    int b = i / NLMK, k = i % NLMK;
    int v = land[k];
    size_t src = ((size_t)b * VNUM + v) * 3;
    size_t dst = (size_t)i * 3;
    lmk[dst + 0] = verts[src + 0];
    lmk[dst + 1] = verts[src + 1];
    lmk[dst + 2] = verts[src + 2];
}

// ============================================================
extern "C" void kernel_launch(void* const* d_in, const int* in_sizes, int n_in,
                              void* d_out, int out_size)
{
    const float* shape = (const float*)d_in[0];
    const float* expr  = (const float*)d_in[1];
    const float* pose  = (const float*)d_in[2];
    const int*   land  = (const int*)  d_in[3];
    const float* vt    = (const float*)d_in[4];
    const float* sd    = (const float*)d_in[5];
    const float* pd    = (const float*)d_in[6];
    const float* Jreg  = (const float*)d_in[7];
    const float* lw    = (const float*)d_in[8];
    const float* eye   = (const float*)d_in[9];
    const float* neck  = (const float*)d_in[10];
    float* out = (float*)d_out;

    cudaFuncSetAttribute(kernG, cudaFuncAttributeMaxDynamicSharedMemorySize, SM_TOT);

    kernF1<<<F1_BLK, 256>>>(sd, vt, pd, Jreg);            // launch 1
    kernB<<<NB / 32, 32>>>(shape, expr, pose, eye, neck); // launch 2
    dim3 gg(NPAD4 / 64, NB / 128);
    kernG<<<gg, 256, SM_TOT>>>(vt, lw, out);              // launch 3
    float* lmk = out + (size_t)NB * VNUM * 3;
    kernD<<<(NB * NLMK + 255) / 256, 256>>>(land, out, lmk);  // launch 4
}

// round 16
// speedup vs baseline: 1.1533x; 1.0706x over previous
#include <cuda_runtime.h>
#include <cuda_bf16.h>
#include <math.h>
#include <stdint.h>

#define VNUM   5023
#define NJ     5
#define NB     1024
#define NSHAPE 100
#define NEXPR  50
#define NBETA  150
#define NLMK   68
#define NPOSE  36
#define JR_COLS 453
#define JRP    2272            // padded NJ*JR_COLS (2265 -> /4 friendly)
#define PD_N   (VNUM * 3)      // 15069

#define KP    192              // padded K: 150 betas + 36 pose feats + 6 zero
#define NPAD4 20096            // 157 * 128 >= 4*VNUM

#define VB      5              // vertices per F1 block
#define F1_BLK  1008           // 1008*5 = 5040 >= 5023
#define NSLOT   8              // Jr accumulator slots

// ---- device scratch ----
__device__ float g_Jr8[NSLOT * JRP];                  // zero at load; kernD re-zeros
__device__ float g_relT[NB * NJ * 12];
__device__ __nv_bfloat16 g_A[NB * KP];                // 0.4 MB
__device__ __nv_bfloat16 g_B4[(size_t)NPAD4 * KP];    // 7.7 MB (c==3 rows stay 0)

__device__ __forceinline__ uint32_t smem_u32(const void* p) {
    uint32_t a;
    asm("{ .reg .u64 t; cvta.to.shared.u64 t, %1; cvt.u32.u64 %0, t; }" : "=r"(a) : "l"(p));
    return a;
}

#define LDSM4(R0, R1, R2, R3, ADDR) \
    asm volatile("ldmatrix.sync.aligned.m8n8.x4.shared.b16 {%0,%1,%2,%3}, [%4];" \
        : "=r"(R0), "=r"(R1), "=r"(R2), "=r"(R3) : "r"(ADDR))

#define MMA16816(C, A0, A1, A2, A3, B0, B1) \
    asm volatile("mma.sync.aligned.m16n8k16.row.col.f32.bf16.bf16.f32 " \
        "{%0,%1,%2,%3},{%4,%5,%6,%7},{%8,%9},{%0,%1,%2,%3};" \
        : "+f"((C)[0]), "+f"((C)[1]), "+f"((C)[2]), "+f"((C)[3]) \
        : "r"(A0), "r"(A1), "r"(A2), "r"(A3), "r"(B0), "r"(B1))

#define CP_ASYNC16(DST, SRC) \
    asm volatile("cp.async.cg.shared.global [%0], [%1], 16;" :: "r"(DST), "l"(SRC))
#define CP_ASYNC_WAIT() \
    asm volatile("cp.async.commit_group;\n\tcp.async.wait_group 0;" ::: "memory")

// ============================================================
// Launch 1 — kernF1: fused B4 build + Jr accumulation.
// 1008 blocks x 256 threads; each block owns 5 vertices.
// sd rows staged once (Jr AND B4); pd slice staged coalesced.
// B4 stores packed bf16x2; c==3 pad rows never written (load-time 0).
// Atomics into slot blockIdx&7 (zeroed by previous replay's kernD).
// ============================================================
__global__ void __launch_bounds__(256) kernF1(
    const float* __restrict__ sd, const float* __restrict__ vt,
    const float* __restrict__ pd, const float* __restrict__ Jreg)
{
    __shared__ float s_sd[VB][456];    // 5 rows x (450 sd | 3 vt | pad)
    __shared__ float s_jr[NJ][VB];
    __shared__ float s_pd[NPOSE][16];  // 36 k-rows x 15 n-values (+pad)
    int tid = threadIdx.x;
    int v0 = blockIdx.x * VB;
    int slot = blockIdx.x & (NSLOT - 1);

    for (int i = tid; i < NJ * VB; i += 256) {
        int j = i / VB, vv = i % VB;
        int v = v0 + vv;
        s_jr[j][vv] = (v < VNUM) ? Jreg[j * VNUM + v] : 0.f;
    }
    // stage 5 sd rows (+vt) coalesced; zero beyond VNUM
    for (int i = tid; i < VB * 456; i += 256) {
        int r = i / 456, c = i - r * 456;
        int v = v0 + r;
        float val = 0.f;
        if (v < VNUM) {
            if (c < 450)      val = sd[v * 450 + c];
            else if (c < 453) val = vt[v * 3 + (c - 450)];
        }
        s_sd[r][c] = val;
    }
    // stage pd slice: row k, lane nn -> pd[k*PD_N + v0*3 + nn]  (coalesced)
    for (int i = tid; i < NPOSE * 16; i += 256) {
        int k = i >> 4, nn = i & 15;
        int ng = v0 * 3 + nn;
        s_pd[k][nn] = (nn < VB * 3 && ng < PD_N) ? pd[(size_t)k * PD_N + ng] : 0.f;
    }
    __syncthreads();

    // --- Jr accumulation ---
    int col0 = tid, col1 = tid + 256;
    float acc[10];
#pragma unroll
    for (int q = 0; q < 10; q++) acc[q] = 0.f;
#pragma unroll
    for (int r = 0; r < VB; r++) {
        float j0 = s_jr[0][r], j1 = s_jr[1][r], j2 = s_jr[2][r];
        float j3 = s_jr[3][r], j4 = s_jr[4][r];
        float x0 = s_sd[r][col0];
        acc[0] = fmaf(j0, x0, acc[0]); acc[1] = fmaf(j1, x0, acc[1]);
        acc[2] = fmaf(j2, x0, acc[2]); acc[3] = fmaf(j3, x0, acc[3]);
        acc[4] = fmaf(j4, x0, acc[4]);
        if (col1 < JR_COLS) {
            float x1 = s_sd[r][col1];
            acc[5] = fmaf(j0, x1, acc[5]); acc[6] = fmaf(j1, x1, acc[6]);
            acc[7] = fmaf(j2, x1, acc[7]); acc[8] = fmaf(j3, x1, acc[8]);
            acc[9] = fmaf(j4, x1, acc[9]);
        }
    }

    // --- B4 build: only the 15 real rows (c < 3); c==3 rows stay zero ---
    for (int i = tid; i < 15 * 96; i += 256) {
        int nl = i / 96;
        int kk = (i - nl * 96) * 2;
        int vl2 = nl / 3, c = nl - vl2 * 3;
        int n = (v0 + vl2) * 4 + c;
        if (n < NPAD4) {
            float f0 = 0.f, f1 = 0.f;
            if (kk < NBETA) {
                f0 = s_sd[vl2][c * NBETA + kk];
                f1 = s_sd[vl2][c * NBETA + kk + 1];
            } else if (kk < NBETA + NPOSE) {
                f0 = s_pd[kk - NBETA][vl2 * 3 + c];
                f1 = (kk + 1 < NBETA + NPOSE) ? s_pd[kk + 1 - NBETA][vl2 * 3 + c] : 0.f;
            }
            __nv_bfloat162 pk;
            pk.x = __float2bfloat16(f0);
            pk.y = __float2bfloat16(f1);
            *(__nv_bfloat162*)(g_B4 + (size_t)n * KP + kk) = pk;
        }
    }

    // --- atomics into slot (126 CTAs per address; fire-and-forget) ---
    float* jr = g_Jr8 + slot * JRP;
#pragma unroll
    for (int j = 0; j < NJ; j++) {
        atomicAdd(&jr[j * JR_COLS + col0], acc[j]);
        if (col1 < JR_COLS) atomicAdd(&jr[j * JR_COLS + col1], acc[5 + j]);
    }
}

// ============================================================
// Launch 2 — kernB: joints, Rodrigues, chain -> g_relT + bf16 A rows.
// 32 blocks x 32 threads.  Slot reduction vectorized (float4).
// ============================================================
#define BP 153

__global__ void __launch_bounds__(32) kernB(
    const float* __restrict__ shape, const float* __restrict__ expr,
    const float* __restrict__ pose, const float* __restrict__ eye,
    const float* __restrict__ neck)
{
    __shared__ float s_jr[JRP];
    __shared__ float s_beta[32 * BP];
    int tid = threadIdx.x;
    int b0 = blockIdx.x * 32;

    // float4 reduction over 8 slots (padded tail is always zero)
    for (int i4 = tid; i4 < JRP / 4; i4 += 32) {
        float4 s = make_float4(0.f, 0.f, 0.f, 0.f);
#pragma unroll
        for (int t = 0; t < NSLOT; t++) {
            float4 v = *(const float4*)(g_Jr8 + t * JRP + i4 * 4);
            s.x += v.x; s.y += v.y; s.z += v.z; s.w += v.w;
        }
        *(float4*)(s_jr + i4 * 4) = s;
    }
    for (int i = tid; i < 32 * NSHAPE; i += 32)
        s_beta[(i / NSHAPE) * BP + (i % NSHAPE)] = shape[b0 * NSHAPE + i];
    for (int i = tid; i < 32 * NEXPR; i += 32)
        s_beta[(i / NEXPR) * BP + NSHAPE + (i % NEXPR)] = expr[b0 * NEXPR + i];
    __syncthreads();

    int b = b0 + tid;
    const float* myb = s_beta + tid * BP;

    float J[NJ][3];
#pragma unroll
    for (int j = 0; j < NJ; j++)
#pragma unroll
        for (int c = 0; c < 3; c++) J[j][c] = s_jr[j * JR_COLS + 450 + c];

    for (int l = 0; l < NBETA; l++) {
        float blv = myb[l];
#pragma unroll
        for (int j = 0; j < NJ; j++)
#pragma unroll
            for (int c = 0; c < 3; c++) J[j][c] = fmaf(s_jr[j * JR_COLS + l], blv, J[j][c]);
    }

    float fp[15];
    fp[0] = pose[b * 6 + 0]; fp[1] = pose[b * 6 + 1]; fp[2] = pose[b * 6 + 2];
    fp[3] = neck[0]; fp[4] = neck[1]; fp[5] = neck[2];
    fp[6] = pose[b * 6 + 3]; fp[7] = pose[b * 6 + 4]; fp[8] = pose[b * 6 + 5];
#pragma unroll
    for (int k = 0; k < 6; k++) fp[9 + k] = eye[k];

    float R[NJ][9];
#pragma unroll
    for (int j = 0; j < NJ; j++) {
        float x = fp[j * 3 + 0], y = fp[j * 3 + 1], z = fp[j * 3 + 2];
        float xa = x + 1e-8f, ya = y + 1e-8f, za = z + 1e-8f;
        float ang = sqrtf(xa * xa + ya * ya + za * za);
        float inv = 1.f / ang;
        float rx = x * inv, ry = y * inv, rz = z * inv;
        float s, c;
        sincosf(ang, &s, &c);
        float t = 1.f - c;
        R[j][0] = 1.f - t * (ry * ry + rz * rz);
        R[j][1] = -s * rz + t * rx * ry;
        R[j][2] =  s * ry + t * rx * rz;
        R[j][3] =  s * rz + t * rx * ry;
        R[j][4] = 1.f - t * (rx * rx + rz * rz);
        R[j][5] = -s * rx + t * ry * rz;
        R[j][6] = -s * ry + t * rx * rz;
        R[j][7] =  s * rx + t * ry * rz;
        R[j][8] = 1.f - t * (rx * rx + ry * ry);
    }

    // --- g_A row: [betas(150) | pose_feature(36) | 0 pad(6)] bf16 ---
    {
        __nv_bfloat16* arow = g_A + (size_t)b * KP;
#pragma unroll 2
        for (int l = 0; l < NBETA; l++) arow[l] = __float2bfloat16(myb[l]);
#pragma unroll
        for (int j = 1; j < NJ; j++)
#pragma unroll
            for (int k = 0; k < 9; k++) {
                float d = (k == 0 || k == 4 || k == 8) ? 1.f : 0.f;
                arow[NBETA + (j - 1) * 9 + k] = __float2bfloat16(R[j][k] - d);
            }
#pragma unroll
        for (int k = NBETA + NPOSE; k < KP; k++) arow[k] = __float2bfloat16(0.f);
    }

    const int par[NJ] = { -1, 0, 1, 1, 1 };
    float rel[NJ][3];
#pragma unroll
    for (int c = 0; c < 3; c++) rel[0][c] = J[0][c];
#pragma unroll
    for (int j = 1; j < NJ; j++)
#pragma unroll
        for (int c = 0; c < 3; c++) rel[j][c] = J[j][c] - J[par[j]][c];

    float cR[NJ][9], ct[NJ][3];
#pragma unroll
    for (int k = 0; k < 9; k++) cR[0][k] = R[0][k];
#pragma unroll
    for (int c = 0; c < 3; c++) ct[0][c] = rel[0][c];
#pragma unroll
    for (int j = 1; j < NJ; j++) {
        int p = par[j];
#pragma unroll
        for (int r = 0; r < 3; r++) {
#pragma unroll
            for (int c = 0; c < 3; c++)
                cR[j][r * 3 + c] = cR[p][r * 3 + 0] * R[j][0 + c]
                                 + cR[p][r * 3 + 1] * R[j][3 + c]
                                 + cR[p][r * 3 + 2] * R[j][6 + c];
            ct[j][r] = cR[p][r * 3 + 0] * rel[j][0] + cR[p][r * 3 + 1] * rel[j][1]
                     + cR[p][r * 3 + 2] * rel[j][2] + ct[p][r];
        }
    }

#pragma unroll
    for (int j = 0; j < NJ; j++)
#pragma unroll
        for (int r = 0; r < 3; r++) {
            float tr = ct[j][r] - (cR[j][r * 3 + 0] * J[j][0] + cR[j][r * 3 + 1] * J[j][1]
                                 + cR[j][r * 3 + 2] * J[j][2]);
            g_relT[b * 60 + j * 12 + r * 4 + 0] = cR[j][r * 3 + 0];
            g_relT[b * 60 + j * 12 + r * 4 + 1] = cR[j][r * 3 + 1];
            g_relT[b * 60 + j * 12 + r * 4 + 2] = cR[j][r * 3 + 2];
            g_relT[b * 60 + j * 12 + r * 4 + 3] = tr;
        }
}

// ============================================================
// Launch 3 — kernG: C[128b x 64n] = A @ B4^T (mma.sync bf16)
// + fused LBS epilogue.  R11 mainloop (69.2us); epilogue staging
// now overlapped: relT via cp.async + w/vt LDGs issued BEFORE the
// accumulator->sC write phase, waited after.
// 256 thr = 8 warps (4b x 2n), warp tile 32b x 32n, 3 CTAs/SM.
// ============================================================
#define SMB_OFF 51200
#define SM_TOT  76800

__global__ void __launch_bounds__(256, 3) kernG(
    const float* __restrict__ vt, const float* __restrict__ lw,
    float* __restrict__ out)
{
    extern __shared__ char smr[];
    uint32_t sb = smem_u32(smr);
    int tid = threadIdx.x;
    int lane = tid & 31, w = tid >> 5;
    int wm = w & 3, wn = w >> 2;          // 4b x 2n grid, warp tile 32b x 32n
    int n0 = blockIdx.x * 64;
    int b0 = blockIdx.y * 128;
    int v0 = n0 >> 2;                     // 16 vertices per tile

    // --- stage A (128x24 uint4) + B (64x24 uint4) via cp.async, pitch 400B ---
    {
        const uint4* gA4 = (const uint4*)(g_A + (size_t)b0 * KP);
        const uint4* gB4 = (const uint4*)(g_B4 + (size_t)n0 * KP);
        for (int i = tid; i < 128 * 24; i += 256) {
            int row = i / 24, q = i - row * 24;
            CP_ASYNC16(sb + row * 400 + q * 16, gA4 + i);
        }
        for (int i = tid; i < 64 * 24; i += 256) {
            int row = i / 24, q = i - row * 24;
            CP_ASYNC16(sb + SMB_OFF + row * 400 + q * 16, gB4 + i);
        }
        CP_ASYNC_WAIT();
    }
    __syncthreads();

    float acc[2][4][4];
#pragma unroll
    for (int a = 0; a < 2; a++)
#pragma unroll
        for (int j = 0; j < 4; j++)
#pragma unroll
            for (int k = 0; k < 4; k++) acc[a][j][k] = 0.f;

    int lrow = lane & 15;
    uint32_t koff = (uint32_t)((lane >> 4) * 16);
    uint32_t aBase = sb + (wm * 32 + lrow) * 400 + koff;
    uint32_t bBase = sb + SMB_OFF + (wn * 32 + lrow) * 400 + koff;

#pragma unroll
    for (int ks = 0; ks < 12; ks++) {
        uint32_t kb = (uint32_t)ks * 32u;
        uint32_t ra[2][4], rb[2][4];
        LDSM4(ra[0][0], ra[0][1], ra[0][2], ra[0][3], aBase + kb);
        LDSM4(ra[1][0], ra[1][1], ra[1][2], ra[1][3], aBase + 16 * 400 + kb);
        LDSM4(rb[0][0], rb[0][1], rb[0][2], rb[0][3], bBase + kb);
        LDSM4(rb[1][0], rb[1][1], rb[1][2], rb[1][3], bBase + 16 * 400 + kb);
#pragma unroll
        for (int a = 0; a < 2; a++)
#pragma unroll
            for (int jj = 0; jj < 2; jj++) {
                MMA16816(acc[a][jj * 2],     ra[a][0], ra[a][1], ra[a][2], ra[a][3],
                         rb[jj][0], rb[jj][2]);
                MMA16816(acc[a][jj * 2 + 1], ra[a][0], ra[a][1], ra[a][2], ra[a][3],
                         rb[jj][1], rb[jj][3]);
            }
    }

    __syncthreads();   // done reading A/B smem

    // --- issue epilogue staging EARLY (overlaps with sC writes) ---
    // relT via cp.async into the dead A region
    {
        const uint4* gRT = (const uint4*)(g_relT + b0 * 60);
        for (int i = tid; i < 1920; i += 256)
            CP_ASYNC16(sb + 34816 + (uint32_t)i * 16, gRT + i);
    }
    // w/vt guarded LDGs into registers (stored after sC writes)
    float wreg = 0.f, vreg = 0.f;
    if (tid < 16 * NJ) {
        int vl = tid / NJ;
        int v = v0 + vl;
        wreg = (v < VNUM) ? lw[v * NJ + (tid % NJ)] : 0.f;
    }
    if (tid < 48) {
        int vl = tid / 3;
        int v = v0 + vl;
        vreg = (v < VNUM) ? vt[v * 3 + (tid % 3)] : 0.f;
    }

    // --- write accumulators to sC [128 x 68] f32 ---
    float* sC = (float*)smr;
#pragma unroll
    for (int a = 0; a < 2; a++) {
        int r = wm * 32 + a * 16 + (lane >> 2);
        int cb = wn * 32 + (lane & 3) * 2;
#pragma unroll
        for (int j = 0; j < 4; j++) {
            int c = cb + j * 8;
            sC[r * 68 + c]           = acc[a][j][0];
            sC[r * 68 + c + 1]       = acc[a][j][1];
            sC[(r + 8) * 68 + c]     = acc[a][j][2];
            sC[(r + 8) * 68 + c + 1] = acc[a][j][3];
        }
    }

    float* sW = (float*)(smr + 65536);
    float* sVT = (float*)(smr + 65856);
    if (tid < 16 * NJ) sW[tid] = wreg;
    if (tid < 48)      sVT[tid] = vreg;
    CP_ASYNC_WAIT();
    __syncthreads();

    float* sRT = (float*)(smr + 34816);

    // --- per (b, v): blend transform (float4 vectorized), apply, store ---
#pragma unroll 4
    for (int it = 0; it < 8; it++) {
        int p = it * 256 + tid;
        int vl = p & 15, bl = p >> 4;
        int v = v0 + vl;
        float4 cv = *(const float4*)(sC + bl * 68 + vl * 4);
        const float4* rt4 = (const float4*)(sRT + bl * 60);   // 15 float4
        float w0 = sW[vl * NJ + 0], w1 = sW[vl * NJ + 1], w2 = sW[vl * NJ + 2];
        float w3 = sW[vl * NJ + 3], w4 = sW[vl * NJ + 4];
        float4 T4[3];
#pragma unroll
        for (int q = 0; q < 3; q++) {
            float4 r0 = rt4[q], r1 = rt4[3 + q], r2 = rt4[6 + q];
            float4 r3 = rt4[9 + q], r4 = rt4[12 + q];
            T4[q].x = fmaf(w0, r0.x, fmaf(w1, r1.x, fmaf(w2, r2.x, fmaf(w3, r3.x, w4 * r4.x))));
            T4[q].y = fmaf(w0, r0.y, fmaf(w1, r1.y, fmaf(w2, r2.y, fmaf(w3, r3.y, w4 * r4.y))));
            T4[q].z = fmaf(w0, r0.z, fmaf(w1, r1.z, fmaf(w2, r2.z, fmaf(w3, r3.z, w4 * r4.z))));
            T4[q].w = fmaf(w0, r0.w, fmaf(w1, r1.w, fmaf(w2, r2.w, fmaf(w3, r3.w, w4 * r4.w))));
        }
        float px = cv.x + sVT[vl * 3 + 0];
        float py = cv.y + sVT[vl * 3 + 1];
        float pz = cv.z + sVT[vl * 3 + 2];
        float ox = fmaf(T4[0].x, px, fmaf(T4[0].y, py, fmaf(T4[0].z, pz, T4[0].w)));
        float oy = fmaf(T4[1].x, px, fmaf(T4[1].y, py, fmaf(T4[1].z, pz, T4[1].w)));
        float oz = fmaf(T4[2].x, px, fmaf(T4[2].y, py, fmaf(T4[2].z, pz, T4[2].w)));
        if (v < VNUM) {
            size_t base = ((size_t)(b0 + bl) * VNUM + v) * 3;
            out[base + 0] = ox; out[base + 1] = oy; out[base + 2] = oz;
        }
    }
}

// ============================================================
// Launch 4 — kernD: landmark gather + Jr-slot re-zero.
// ============================================================
__global__ void kernD(const int* __restrict__ land, const float* __restrict__ verts,
                      float* __restrict__ lmk)
{
    if (blockIdx.x < NSLOT) {
        int base = blockIdx.x * JRP;
        for (int i = threadIdx.x; i < JRP; i += blockDim.x)
            g_Jr8[base + i] = 0.f;
    }
    int i = blockIdx.x * blockDim.x + threadIdx.x;
    if (i >= NB * NLMK) return;
    int b = i / NLMK, k = i % NLMK;
    int v = land[k];
    size_t src = ((size_t)b * VNUM + v) * 3;
    size_t dst = (size_t)i * 3;
    lmk[dst + 0] = verts[src + 0];
    lmk[dst + 1] = verts[src + 1];
    lmk[dst + 2] = verts[src + 2];
}

// ============================================================
extern "C" void kernel_launch(void* const* d_in, const int* in_sizes, int n_in,
                              void* d_out, int out_size)
{
    const float* shape = (const float*)d_in[0];
    const float* expr  = (const float*)d_in[1];
    const float* pose  = (const float*)d_in[2];
    const int*   land  = (const int*)  d_in[3];
    const float* vt    = (const float*)d_in[4];
    const float* sd    = (const float*)d_in[5];
    const float* pd    = (const float*)d_in[6];
    const float* Jreg  = (const float*)d_in[7];
    const float* lw    = (const float*)d_in[8];
    const float* eye   = (const float*)d_in[9];
    const float* neck  = (const float*)d_in[10];
    float* out = (float*)d_out;

    cudaFuncSetAttribute(kernG, cudaFuncAttributeMaxDynamicSharedMemorySize, SM_TOT);

    kernF1<<<F1_BLK, 256>>>(sd, vt, pd, Jreg);            // launch 1
    kernB<<<NB / 32, 32>>>(shape, expr, pose, eye, neck); // launch 2
    dim3 gg(NPAD4 / 64, NB / 128);
    kernG<<<gg, 256, SM_TOT>>>(vt, lw, out);              // launch 3
    float* lmk = out + (size_t)NB * VNUM * 3;
    kernD<<<(NB * NLMK + 255) / 256, 256>>>(land, out, lmk);  // launch 4
}

// round 17
// speedup vs baseline: 1.1558x; 1.0021x over previous
#include <cuda_runtime.h>
#include <cuda_bf16.h>
#include <math.h>
#include <stdint.h>

#define VNUM   5023
#define NJ     5
#define NB     1024
#define NSHAPE 100
#define NEXPR  50
#define NBETA  150
#define NLMK   68
#define NPOSE  36
#define JR_COLS 453
#define JRP    2272            // padded NJ*JR_COLS (2265 -> /4 friendly)
#define PD_N   (VNUM * 3)      // 15069

#define KP    192              // padded K: 150 betas + 36 pose feats + 6 zero
#define NPAD4 20096            // 157 * 128 >= 4*VNUM

#define VB      5              // vertices per F1 block
#define F1_BLK  1008           // 1008*5 = 5040 >= 5023
#define NSLOT   8              // Jr accumulator slots

// ---- device scratch ----
__device__ float g_Jr8[NSLOT * JRP];                  // zero at load; kernD re-zeros
__device__ float g_relT[NB * NJ * 12];
__device__ __nv_bfloat16 g_A[NB * KP];                // 0.4 MB
__device__ __nv_bfloat16 g_B4[(size_t)NPAD4 * KP];    // 7.7 MB (c==3 rows stay 0)

__device__ __forceinline__ uint32_t smem_u32(const void* p) {
    uint32_t a;
    asm("{ .reg .u64 t; cvta.to.shared.u64 t, %1; cvt.u32.u64 %0, t; }" : "=r"(a) : "l"(p));
    return a;
}

#define LDSM4(R0, R1, R2, R3, ADDR) \
    asm volatile("ldmatrix.sync.aligned.m8n8.x4.shared.b16 {%0,%1,%2,%3}, [%4];" \
        : "=r"(R0), "=r"(R1), "=r"(R2), "=r"(R3) : "r"(ADDR))

#define MMA16816(C, A0, A1, A2, A3, B0, B1) \
    asm volatile("mma.sync.aligned.m16n8k16.row.col.f32.bf16.bf16.f32 " \
        "{%0,%1,%2,%3},{%4,%5,%6,%7},{%8,%9},{%0,%1,%2,%3};" \
        : "+f"((C)[0]), "+f"((C)[1]), "+f"((C)[2]), "+f"((C)[3]) \
        : "r"(A0), "r"(A1), "r"(A2), "r"(A3), "r"(B0), "r"(B1))

#define CP_ASYNC16(DST, SRC) \
    asm volatile("cp.async.cg.shared.global [%0], [%1], 16;" :: "r"(DST), "l"(SRC))
#define CP_ASYNC_WAIT() \
    asm volatile("cp.async.commit_group;\n\tcp.async.wait_group 0;" ::: "memory")

// ============================================================
// Launch 1 — kernF1: fused B4 build + Jr accumulation.
// 1008 blocks x 256 threads; each block owns 5 vertices.
// ============================================================
__global__ void __launch_bounds__(256) kernF1(
    const float* __restrict__ sd, const float* __restrict__ vt,
    const float* __restrict__ pd, const float* __restrict__ Jreg)
{
    __shared__ float s_sd[VB][456];    // 5 rows x (450 sd | 3 vt | pad)
    __shared__ float s_jr[NJ][VB];
    __shared__ float s_pd[NPOSE][16];  // 36 k-rows x 15 n-values (+pad)
    int tid = threadIdx.x;
    int v0 = blockIdx.x * VB;
    int slot = blockIdx.x & (NSLOT - 1);

    for (int i = tid; i < NJ * VB; i += 256) {
        int j = i / VB, vv = i % VB;
        int v = v0 + vv;
        s_jr[j][vv] = (v < VNUM) ? Jreg[j * VNUM + v] : 0.f;
    }
    // stage 5 sd rows (+vt) coalesced; zero beyond VNUM
    for (int i = tid; i < VB * 456; i += 256) {
        int r = i / 456, c = i - r * 456;
        int v = v0 + r;
        float val = 0.f;
        if (v < VNUM) {
            if (c < 450)      val = sd[v * 450 + c];
            else if (c < 453) val = vt[v * 3 + (c - 450)];
        }
        s_sd[r][c] = val;
    }
    // stage pd slice: row k, lane nn -> pd[k*PD_N + v0*3 + nn]  (coalesced)
    for (int i = tid; i < NPOSE * 16; i += 256) {
        int k = i >> 4, nn = i & 15;
        int ng = v0 * 3 + nn;
        s_pd[k][nn] = (nn < VB * 3 && ng < PD_N) ? pd[(size_t)k * PD_N + ng] : 0.f;
    }
    __syncthreads();

    // --- Jr accumulation ---
    int col0 = tid, col1 = tid + 256;
    float acc[10];
#pragma unroll
    for (int q = 0; q < 10; q++) acc[q] = 0.f;
#pragma unroll
    for (int r = 0; r < VB; r++) {
        float j0 = s_jr[0][r], j1 = s_jr[1][r], j2 = s_jr[2][r];
        float j3 = s_jr[3][r], j4 = s_jr[4][r];
        float x0 = s_sd[r][col0];
        acc[0] = fmaf(j0, x0, acc[0]); acc[1] = fmaf(j1, x0, acc[1]);
        acc[2] = fmaf(j2, x0, acc[2]); acc[3] = fmaf(j3, x0, acc[3]);
        acc[4] = fmaf(j4, x0, acc[4]);
        if (col1 < JR_COLS) {
            float x1 = s_sd[r][col1];
            acc[5] = fmaf(j0, x1, acc[5]); acc[6] = fmaf(j1, x1, acc[6]);
            acc[7] = fmaf(j2, x1, acc[7]); acc[8] = fmaf(j3, x1, acc[8]);
            acc[9] = fmaf(j4, x1, acc[9]);
        }
    }

    // --- B4 build: only the 15 real rows (c < 3); c==3 rows stay zero ---
    for (int i = tid; i < 15 * 96; i += 256) {
        int nl = i / 96;
        int kk = (i - nl * 96) * 2;
        int vl2 = nl / 3, c = nl - vl2 * 3;
        int n = (v0 + vl2) * 4 + c;
        if (n < NPAD4) {
            float f0 = 0.f, f1 = 0.f;
            if (kk < NBETA) {
                f0 = s_sd[vl2][c * NBETA + kk];
                f1 = s_sd[vl2][c * NBETA + kk + 1];
            } else if (kk < NBETA + NPOSE) {
                f0 = s_pd[kk - NBETA][vl2 * 3 + c];
                f1 = (kk + 1 < NBETA + NPOSE) ? s_pd[kk + 1 - NBETA][vl2 * 3 + c] : 0.f;
            }
            __nv_bfloat162 pk;
            pk.x = __float2bfloat16(f0);
            pk.y = __float2bfloat16(f1);
            *(__nv_bfloat162*)(g_B4 + (size_t)n * KP + kk) = pk;
        }
    }

    // --- atomics into slot (126 CTAs per address; fire-and-forget) ---
    float* jr = g_Jr8 + slot * JRP;
#pragma unroll
    for (int j = 0; j < NJ; j++) {
        atomicAdd(&jr[j * JR_COLS + col0], acc[j]);
        if (col1 < JR_COLS) atomicAdd(&jr[j * JR_COLS + col1], acc[5 + j]);
    }
}

// ============================================================
// Launch 2 — kernB: joints, Rodrigues, chain -> g_relT + bf16 A rows.
// 32 blocks x 32 threads.  Slot reduction vectorized (float4).
// ============================================================
#define BP 153

__global__ void __launch_bounds__(32) kernB(
    const float* __restrict__ shape, const float* __restrict__ expr,
    const float* __restrict__ pose, const float* __restrict__ eye,
    const float* __restrict__ neck)
{
    __shared__ float s_jr[JRP];
    __shared__ float s_beta[32 * BP];
    int tid = threadIdx.x;
    int b0 = blockIdx.x * 32;

    // float4 reduction over 8 slots (padded tail is always zero)
    for (int i4 = tid; i4 < JRP / 4; i4 += 32) {
        float4 s = make_float4(0.f, 0.f, 0.f, 0.f);
#pragma unroll
        for (int t = 0; t < NSLOT; t++) {
            float4 v = *(const float4*)(g_Jr8 + t * JRP + i4 * 4);
            s.x += v.x; s.y += v.y; s.z += v.z; s.w += v.w;
        }
        *(float4*)(s_jr + i4 * 4) = s;
    }
    for (int i = tid; i < 32 * NSHAPE; i += 32)
        s_beta[(i / NSHAPE) * BP + (i % NSHAPE)] = shape[b0 * NSHAPE + i];
    for (int i = tid; i < 32 * NEXPR; i += 32)
        s_beta[(i / NEXPR) * BP + NSHAPE + (i % NEXPR)] = expr[b0 * NEXPR + i];
    __syncthreads();

    int b = b0 + tid;
    const float* myb = s_beta + tid * BP;

    float J[NJ][3];
#pragma unroll
    for (int j = 0; j < NJ; j++)
#pragma unroll
        for (int c = 0; c < 3; c++) J[j][c] = s_jr[j * JR_COLS + 450 + c];

    for (int l = 0; l < NBETA; l++) {
        float blv = myb[l];
#pragma unroll
        for (int j = 0; j < NJ; j++)
#pragma unroll
            for (int c = 0; c < 3; c++) J[j][c] = fmaf(s_jr[j * JR_COLS + l], blv, J[j][c]);
    }

    float fp[15];
    fp[0] = pose[b * 6 + 0]; fp[1] = pose[b * 6 + 1]; fp[2] = pose[b * 6 + 2];
    fp[3] = neck[0]; fp[4] = neck[1]; fp[5] = neck[2];
    fp[6] = pose[b * 6 + 3]; fp[7] = pose[b * 6 + 4]; fp[8] = pose[b * 6 + 5];
#pragma unroll
    for (int k = 0; k < 6; k++) fp[9 + k] = eye[k];

    float R[NJ][9];
#pragma unroll
    for (int j = 0; j < NJ; j++) {
        float x = fp[j * 3 + 0], y = fp[j * 3 + 1], z = fp[j * 3 + 2];
        float xa = x + 1e-8f, ya = y + 1e-8f, za = z + 1e-8f;
        float ang = sqrtf(xa * xa + ya * ya + za * za);
        float inv = 1.f / ang;
        float rx = x * inv, ry = y * inv, rz = z * inv;
        float s, c;
        sincosf(ang, &s, &c);
        float t = 1.f - c;
        R[j][0] = 1.f - t * (ry * ry + rz * rz);
        R[j][1] = -s * rz + t * rx * ry;
        R[j][2] =  s * ry + t * rx * rz;
        R[j][3] =  s * rz + t * rx * ry;
        R[j][4] = 1.f - t * (rx * rx + rz * rz);
        R[j][5] = -s * rx + t * ry * rz;
        R[j][6] = -s * ry + t * rx * rz;
        R[j][7] =  s * rx + t * ry * rz;
        R[j][8] = 1.f - t * (rx * rx + ry * ry);
    }

    // --- g_A row: [betas(150) | pose_feature(36) | 0 pad(6)] bf16 ---
    {
        __nv_bfloat16* arow = g_A + (size_t)b * KP;
#pragma unroll 2
        for (int l = 0; l < NBETA; l++) arow[l] = __float2bfloat16(myb[l]);
#pragma unroll
        for (int j = 1; j < NJ; j++)
#pragma unroll
            for (int k = 0; k < 9; k++) {
                float d = (k == 0 || k == 4 || k == 8) ? 1.f : 0.f;
                arow[NBETA + (j - 1) * 9 + k] = __float2bfloat16(R[j][k] - d);
            }
#pragma unroll
        for (int k = NBETA + NPOSE; k < KP; k++) arow[k] = __float2bfloat16(0.f);
    }

    const int par[NJ] = { -1, 0, 1, 1, 1 };
    float rel[NJ][3];
#pragma unroll
    for (int c = 0; c < 3; c++) rel[0][c] = J[0][c];
#pragma unroll
    for (int j = 1; j < NJ; j++)
#pragma unroll
        for (int c = 0; c < 3; c++) rel[j][c] = J[j][c] - J[par[j]][c];

    float cR[NJ][9], ct[NJ][3];
#pragma unroll
    for (int k = 0; k < 9; k++) cR[0][k] = R[0][k];
#pragma unroll
    for (int c = 0; c < 3; c++) ct[0][c] = rel[0][c];
#pragma unroll
    for (int j = 1; j < NJ; j++) {
        int p = par[j];
#pragma unroll
        for (int r = 0; r < 3; r++) {
#pragma unroll
            for (int c = 0; c < 3; c++)
                cR[j][r * 3 + c] = cR[p][r * 3 + 0] * R[j][0 + c]
                                 + cR[p][r * 3 + 1] * R[j][3 + c]
                                 + cR[p][r * 3 + 2] * R[j][6 + c];
            ct[j][r] = cR[p][r * 3 + 0] * rel[j][0] + cR[p][r * 3 + 1] * rel[j][1]
                     + cR[p][r * 3 + 2] * rel[j][2] + ct[p][r];
        }
    }

#pragma unroll
    for (int j = 0; j < NJ; j++)
#pragma unroll
        for (int r = 0; r < 3; r++) {
            float tr = ct[j][r] - (cR[j][r * 3 + 0] * J[j][0] + cR[j][r * 3 + 1] * J[j][1]
                                 + cR[j][r * 3 + 2] * J[j][2]);
            g_relT[b * 60 + j * 12 + r * 4 + 0] = cR[j][r * 3 + 0];
            g_relT[b * 60 + j * 12 + r * 4 + 1] = cR[j][r * 3 + 1];
            g_relT[b * 60 + j * 12 + r * 4 + 2] = cR[j][r * 3 + 2];
            g_relT[b * 60 + j * 12 + r * 4 + 3] = tr;
        }
}

// ============================================================
// Launch 3 — kernG: C[128b x 64n] = A @ B4^T (mma.sync bf16)
// + fused LBS epilogue.  w/vt LDGs hoisted to kernel entry (latency
// hidden under the whole mainloop); relT staged via cp.async during
// the sC write phase.
// 256 thr = 8 warps (4b x 2n), warp tile 32b x 32n, 3 CTAs/SM.
// ============================================================
#define SMB_OFF 51200
#define SM_TOT  76800

__global__ void __launch_bounds__(256, 3) kernG(
    const float* __restrict__ vt, const float* __restrict__ lw,
    float* __restrict__ out)
{
    extern __shared__ char smr[];
    uint32_t sb = smem_u32(smr);
    int tid = threadIdx.x;
    int lane = tid & 31, w = tid >> 5;
    int wm = w & 3, wn = w >> 2;          // 4b x 2n grid, warp tile 32b x 32n
    int n0 = blockIdx.x * 64;
    int b0 = blockIdx.y * 128;
    int v0 = n0 >> 2;                     // 16 vertices per tile

    // --- hoisted epilogue LDGs: issue at kernel entry, hidden by GEMM ---
    float wreg = 0.f, vreg = 0.f;
    if (tid < 16 * NJ) {
        int vl = tid / NJ;
        int v = v0 + vl;
        wreg = (v < VNUM) ? lw[v * NJ + (tid % NJ)] : 0.f;
    }
    if (tid < 48) {
        int vl = tid / 3;
        int v = v0 + vl;
        vreg = (v < VNUM) ? vt[v * 3 + (tid % 3)] : 0.f;
    }

    // --- stage A (128x24 uint4) + B (64x24 uint4) via cp.async, pitch 400B ---
    {
        const uint4* gA4 = (const uint4*)(g_A + (size_t)b0 * KP);
        const uint4* gB4 = (const uint4*)(g_B4 + (size_t)n0 * KP);
        for (int i = tid; i < 128 * 24; i += 256) {
            int row = i / 24, q = i - row * 24;
            CP_ASYNC16(sb + row * 400 + q * 16, gA4 + i);
        }
        for (int i = tid; i < 64 * 24; i += 256) {
            int row = i / 24, q = i - row * 24;
            CP_ASYNC16(sb + SMB_OFF + row * 400 + q * 16, gB4 + i);
        }
        CP_ASYNC_WAIT();
    }
    __syncthreads();

    float acc[2][4][4];
#pragma unroll
    for (int a = 0; a < 2; a++)
#pragma unroll
        for (int j = 0; j < 4; j++)
#pragma unroll
            for (int k = 0; k < 4; k++) acc[a][j][k] = 0.f;

    int lrow = lane & 15;
    uint32_t koff = (uint32_t)((lane >> 4) * 16);
    uint32_t aBase = sb + (wm * 32 + lrow) * 400 + koff;
    uint32_t bBase = sb + SMB_OFF + (wn * 32 + lrow) * 400 + koff;

#pragma unroll
    for (int ks = 0; ks < 12; ks++) {
        uint32_t kb = (uint32_t)ks * 32u;
        uint32_t ra[2][4], rb[2][4];
        LDSM4(ra[0][0], ra[0][1], ra[0][2], ra[0][3], aBase + kb);
        LDSM4(ra[1][0], ra[1][1], ra[1][2], ra[1][3], aBase + 16 * 400 + kb);
        LDSM4(rb[0][0], rb[0][1], rb[0][2], rb[0][3], bBase + kb);
        LDSM4(rb[1][0], rb[1][1], rb[1][2], rb[1][3], bBase + 16 * 400 + kb);
#pragma unroll
        for (int a = 0; a < 2; a++)
#pragma unroll
            for (int jj = 0; jj < 2; jj++) {
                MMA16816(acc[a][jj * 2],     ra[a][0], ra[a][1], ra[a][2], ra[a][3],
                         rb[jj][0], rb[jj][2]);
                MMA16816(acc[a][jj * 2 + 1], ra[a][0], ra[a][1], ra[a][2], ra[a][3],
                         rb[jj][1], rb[jj][3]);
            }
    }

    __syncthreads();   // done reading A/B smem

    // --- issue relT staging (cp.async into dead A region) ---
    {
        const uint4* gRT = (const uint4*)(g_relT + b0 * 60);
        for (int i = tid; i < 1920; i += 256)
            CP_ASYNC16(sb + 34816 + (uint32_t)i * 16, gRT + i);
    }

    // --- write accumulators to sC [128 x 68] f32 ---
    float* sC = (float*)smr;
#pragma unroll
    for (int a = 0; a < 2; a++) {
        int r = wm * 32 + a * 16 + (lane >> 2);
        int cb = wn * 32 + (lane & 3) * 2;
#pragma unroll
        for (int j = 0; j < 4; j++) {
            int c = cb + j * 8;
            sC[r * 68 + c]           = acc[a][j][0];
            sC[r * 68 + c + 1]       = acc[a][j][1];
            sC[(r + 8) * 68 + c]     = acc[a][j][2];
            sC[(r + 8) * 68 + c + 1] = acc[a][j][3];
        }
    }

    float* sW = (float*)(smr + 65536);
    float* sVT = (float*)(smr + 65856);
    if (tid < 16 * NJ) sW[tid] = wreg;
    if (tid < 48)      sVT[tid] = vreg;
    CP_ASYNC_WAIT();
    __syncthreads();

    float* sRT = (float*)(smr + 34816);

    // --- per (b, v): blend transform (float4 vectorized), apply, store ---
#pragma unroll 4
    for (int it = 0; it < 8; it++) {
        int p = it * 256 + tid;
        int vl = p & 15, bl = p >> 4;
        int v = v0 + vl;
        float4 cv = *(const float4*)(sC + bl * 68 + vl * 4);
        const float4* rt4 = (const float4*)(sRT + bl * 60);   // 15 float4
        float w0 = sW[vl * NJ + 0], w1 = sW[vl * NJ + 1], w2 = sW[vl * NJ + 2];
        float w3 = sW[vl * NJ + 3], w4 = sW[vl * NJ + 4];
        float4 T4[3];
#pragma unroll
        for (int q = 0; q < 3; q++) {
            float4 r0 = rt4[q], r1 = rt4[3 + q], r2 = rt4[6 + q];
            float4 r3 = rt4[9 + q], r4 = rt4[12 + q];
            T4[q].x = fmaf(w0, r0.x, fmaf(w1, r1.x, fmaf(w2, r2.x, fmaf(w3, r3.x, w4 * r4.x))));
            T4[q].y = fmaf(w0, r0.y, fmaf(w1, r1.y, fmaf(w2, r2.y, fmaf(w3, r3.y, w4 * r4.y))));
            T4[q].z = fmaf(w0, r0.z, fmaf(w1, r1.z, fmaf(w2, r2.z, fmaf(w3, r3.z, w4 * r4.z))));
            T4[q].w = fmaf(w0, r0.w, fmaf(w1, r1.w, fmaf(w2, r2.w, fmaf(w3, r3.w, w4 * r4.w))));
        }
        float px = cv.x + sVT[vl * 3 + 0];
        float py = cv.y + sVT[vl * 3 + 1];
        float pz = cv.z + sVT[vl * 3 + 2];
        float ox = fmaf(T4[0].x, px, fmaf(T4[0].y, py, fmaf(T4[0].z, pz, T4[0].w)));
        float oy = fmaf(T4[1].x, px, fmaf(T4[1].y, py, fmaf(T4[1].z, pz, T4[1].w)));
        float oz = fmaf(T4[2].x, px, fmaf(T4[2].y, py, fmaf(T4[2].z, pz, T4[2].w)));
        if (v < VNUM) {
            size_t base = ((size_t)(b0 + bl) * VNUM + v) * 3;
            out[base + 0] = ox; out[base + 1] = oy; out[base + 2] = oz;
        }
    }
}

// ============================================================
// Launch 4 — kernD: landmark gather (1 scalar/thread, 3x parallelism)
// + Jr-slot re-zero.
// ============================================================
__global__ void kernD(const int* __restrict__ land, const float* __restrict__ verts,
                      float* __restrict__ lmk)
{
    if (blockIdx.x < NSLOT) {
        int base = blockIdx.x * JRP;
        for (int i = threadIdx.x; i < JRP; i += blockDim.x)
            g_Jr8[base + i] = 0.f;
    }
    int i = blockIdx.x * blockDim.x + threadIdx.x;
    if (i >= NB * NLMK * 3) return;
    int c = i % 3;
    int bk = i / 3;
    int b = bk / NLMK, k = bk % NLMK;
    int v = land[k];
    lmk[i] = verts[((size_t)b * VNUM + v) * 3 + c];
}

// ============================================================
extern "C" void kernel_launch(void* const* d_in, const int* in_sizes, int n_in,
                              void* d_out, int out_size)
{
    const float* shape = (const float*)d_in[0];
    const float* expr  = (const float*)d_in[1];
    const float* pose  = (const float*)d_in[2];
    const int*   land  = (const int*)  d_in[3];
    const float* vt    = (const float*)d_in[4];
    const float* sd    = (const float*)d_in[5];
    const float* pd    = (const float*)d_in[6];
    const float* Jreg  = (const float*)d_in[7];
    const float* lw    = (const float*)d_in[8];
    const float* eye   = (const float*)d_in[9];
    const float* neck  = (const float*)d_in[10];
    float* out = (float*)d_out;

    cudaFuncSetAttribute(kernG, cudaFuncAttributeMaxDynamicSharedMemorySize, SM_TOT);

    kernF1<<<F1_BLK, 256>>>(sd, vt, pd, Jreg);            // launch 1
    kernB<<<NB / 32, 32>>>(shape, expr, pose, eye, neck); // launch 2
    dim3 gg(NPAD4 / 64, NB / 128);
    kernG<<<gg, 256, SM_TOT>>>(vt, lw, out);              // launch 3
    float* lmk = out + (size_t)NB * VNUM * 3;
    kernD<<<(NB * NLMK * 3 + 255) / 256, 256>>>(land, out, lmk);  // launch 4
}